// round 9
// baseline (speedup 1.0000x reference)
#include <cuda_runtime.h>
#include <cuda_bf16.h>

#define BATCH 8
#define CH    128
#define MIDC  64
#define OUTC  128
#define TN    2048

typedef unsigned long long u64;
typedef unsigned int u32;

// ---------------------------------------------------------------------------
// Scratch (device globals; allocation-free per harness rules)
// ---------------------------------------------------------------------------
__device__ __nv_bfloat16 g_thhi[BATCH * TN * MIDC];     // theta hi [b][q][m]
__device__ __nv_bfloat16 g_thlo[BATCH * TN * MIDC];
__device__ __nv_bfloat16 g_phhi[BATCH * TN * MIDC];     // phi hi [b][k][m]
__device__ __nv_bfloat16 g_phlo[BATCH * TN * MIDC];
__device__ float         g_g   [BATCH * TN * MIDC];     // g fp32 [b][k][m]
__device__ __nv_bfloat16 g_Ehi [(size_t)BATCH * TN * TN]; // exp(s) bf16 [b][q][k]
__device__ float g_Zp  [16 * BATCH * TN];
__device__ __nv_bfloat16 g_gsThi[BATCH * MIDC * TN];    // (g*invZ)^T bf16 [b][m][k]
__device__ float g_yT [BATCH * MIDC * TN];              // y^T [b][m][q]
__device__ float g_ref[BATCH * TN * OUTC];              // [b][q][o]

// ---------------------------------------------------------------------------
// PTX helpers (base ISA only)
// ---------------------------------------------------------------------------
__device__ __forceinline__ u32 smem_u32(const void* p) {
    u32 a; asm("{ .reg .u64 t; cvta.to.shared.u64 t, %1; cvt.u32.u64 %0, t; }"
               : "=r"(a) : "l"(p)); return a;
}
#define SWZ128(x) ((x) ^ (((x) >> 3) & 0x70))

__device__ __forceinline__ void ldsm4(u32* r, u32 addr) {
    asm volatile("ldmatrix.sync.aligned.m8n8.x4.shared.b16 {%0,%1,%2,%3}, [%4];"
        : "=r"(r[0]), "=r"(r[1]), "=r"(r[2]), "=r"(r[3]) : "r"(addr));
}
__device__ __forceinline__ void mma16816(float* d, const u32* a, u32 b0, u32 b1) {
    asm volatile("mma.sync.aligned.m16n8k16.row.col.f32.bf16.bf16.f32 "
        "{%0,%1,%2,%3}, {%4,%5,%6,%7}, {%8,%9}, {%0,%1,%2,%3};"
        : "+f"(d[0]), "+f"(d[1]), "+f"(d[2]), "+f"(d[3])
        : "r"(a[0]), "r"(a[1]), "r"(a[2]), "r"(a[3]), "r"(b0), "r"(b1));
}
#define CPA16(dst, src) \
    asm volatile("cp.async.cg.shared.global [%0], [%1], 16;" \
                 :: "r"(dst), "l"(src) : "memory")
#define CPA_COMMIT() asm volatile("cp.async.commit_group;" ::: "memory")

// fp32x2 + fast exp helpers
__device__ __forceinline__ u64 splat2(float x) {
    u64 r; asm("mov.b64 %0,{%1,%1};" : "=l"(r) : "f"(x)); return r;
}
__device__ __forceinline__ u64 fma2_(u64 a, u64 b, u64 c) {
    u64 d; asm("fma.rn.f32x2 %0,%1,%2,%3;" : "=l"(d) : "l"(a), "l"(b), "l"(c)); return d;
}
__device__ __forceinline__ void upk2(u64 p, float& a, float& b) {
    asm("mov.b64 {%0,%1},%2;" : "=f"(a), "=f"(b) : "l"(p));
}
__device__ __forceinline__ float fexp(float x) {
    const float L2E = 1.4426950408889634f;
    float z = fmaf(x, L2E, 12582912.0f);
    float n = z - 12582912.0f;
    float f = fmaf(x, L2E, -n);
    float p =          1.3333558146e-3f;
    p = fmaf(p, f,     9.6181291076e-3f);
    p = fmaf(p, f,     5.5504108665e-2f);
    p = fmaf(p, f,     2.4022650696e-1f);
    p = fmaf(p, f,     6.9314718056e-1f);
    p = fmaf(p, f,     1.0f);
    int ni = __float_as_int(z) - 0x4B400000;
    return p * __int_as_float((ni + 127) << 23);
}
__device__ __forceinline__ u32 pkbf(__nv_bfloat16 a, __nv_bfloat16 b) {
    return (u32)__bfloat16_as_ushort(a) | ((u32)__bfloat16_as_ushort(b) << 16);
}
__device__ __forceinline__ u32 pk_hi2(float x, float y) {
    return pkbf(__float2bfloat16(x), __float2bfloat16(y));
}
__device__ __forceinline__ u32 pk_lo2(float x, float y) {
    __nv_bfloat16 hx = __float2bfloat16(x), hy = __float2bfloat16(y);
    return pkbf(__float2bfloat16(x - __bfloat162float(hx)),
                __float2bfloat16(y - __bfloat162float(hy)));
}

// ---------------------------------------------------------------------------
// 1) Projections: relu(W[64x128]*pc[128x2048]+b).
//    theta,phi -> bf16 hi/lo [tn][64];  g -> fp32 [tn][64].
// ---------------------------------------------------------------------------
__global__ void __launch_bounds__(256)
proj_kernel(const float* __restrict__ pc,
            const float* __restrict__ tw, const float* __restrict__ tb,
            const float* __restrict__ pw, const float* __restrict__ pb,
            const float* __restrict__ gw, const float* __restrict__ gb)
{
    __shared__ float As[32 * 64];
    __shared__ float Bs[32 * 128];
    const int b = blockIdx.z, pj = blockIdx.y;
    const int n0 = blockIdx.x * 128;
    const float *W, *bi;
    if (pj == 0)      { W = tw; bi = tb; }
    else if (pj == 1) { W = pw; bi = pb; }
    else              { W = gw; bi = gb; }
    const float* pcb = pc + (size_t)b * CH * TN;
    const int tid = threadIdx.x;
    const int tx = tid & 15, ty = tid >> 4;

    u64 acc[4][4];
#pragma unroll
    for (int i = 0; i < 4; i++)
#pragma unroll
        for (int j = 0; j < 4; j++) acc[i][j] = 0ULL;

    for (int ct = 0; ct < 128; ct += 32) {
#pragma unroll
        for (int t = 0; t < 2; t++) {
            int f4 = tid + t * 256;
            int m = f4 >> 3, c4 = (f4 & 7) << 2;
            float4 w4 = *(const float4*)&W[m * 128 + ct + c4];
            As[(c4 + 0) * 64 + m] = w4.x;  As[(c4 + 1) * 64 + m] = w4.y;
            As[(c4 + 2) * 64 + m] = w4.z;  As[(c4 + 3) * 64 + m] = w4.w;
        }
#pragma unroll
        for (int t = 0; t < 4; t++) {
            int f4 = tid + t * 256;
            int cc = f4 >> 5, c4 = (f4 & 31) << 2;
            *(float4*)&Bs[cc * 128 + c4] =
                *(const float4*)&pcb[(size_t)(ct + cc) * TN + n0 + c4];
        }
        __syncthreads();
#pragma unroll 8
        for (int cc = 0; cc < 32; cc++) {
            float4 av = *(float4*)&As[cc * 64 + ty * 4];
            ulonglong2 b01 = *(ulonglong2*)&Bs[cc * 128 + tx * 8];
            ulonglong2 b23 = *(ulonglong2*)&Bs[cc * 128 + tx * 8 + 4];
            u64 aa[4] = { splat2(av.x), splat2(av.y), splat2(av.z), splat2(av.w) };
            u64 bb[4] = { b01.x, b01.y, b23.x, b23.y };
#pragma unroll
            for (int i = 0; i < 4; i++)
#pragma unroll
                for (int j = 0; j < 4; j++)
                    acc[i][j] = fma2_(aa[i], bb[j], acc[i][j]);
        }
        __syncthreads();
    }

    float v[4][8];
#pragma unroll
    for (int i = 0; i < 4; i++) {
#pragma unroll
        for (int j2 = 0; j2 < 4; j2++) upk2(acc[i][j2], v[i][2 * j2], v[i][2 * j2 + 1]);
        float bv = bi[ty * 4 + i];
#pragma unroll
        for (int j = 0; j < 8; j++) v[i][j] = fmaxf(v[i][j] + bv, 0.f);
    }
    if (pj < 2) {
        __nv_bfloat16* oh = (pj == 0 ? g_thhi : g_phhi) + (size_t)b * TN * MIDC;
        __nv_bfloat16* ol = (pj == 0 ? g_thlo : g_phlo) + (size_t)b * TN * MIDC;
#pragma unroll
        for (int j = 0; j < 8; j++) {
            int tn = n0 + tx * 8 + j;
            *(uint2*)&oh[(size_t)tn * MIDC + ty * 4] =
                make_uint2(pk_hi2(v[0][j], v[1][j]), pk_hi2(v[2][j], v[3][j]));
            *(uint2*)&ol[(size_t)tn * MIDC + ty * 4] =
                make_uint2(pk_lo2(v[0][j], v[1][j]), pk_lo2(v[2][j], v[3][j]));
        }
    } else {
        float* ob = g_g + (size_t)b * TN * MIDC;
#pragma unroll
        for (int j = 0; j < 8; j++)
            *(float4*)&ob[(size_t)(n0 + tx * 8 + j) * MIDC + ty * 4] =
                make_float4(v[0][j], v[1][j], v[2][j], v[3][j]);
    }
}

// ---------------------------------------------------------------------------
// 2) scores via warp-MMA bf16 3-pass + fused exp + register colsum.
//    Stores only E hi (bf16). smem: operands 64KB; staging/red overlay.
// ---------------------------------------------------------------------------
#define SC_SMEM 65536

__global__ void __launch_bounds__(256)
scores_kernel()
{
    extern __shared__ char smem[];
    const u32 sb = smem_u32(smem);
    const int b = blockIdx.z, qt = blockIdx.y, kt = blockIdx.x;
    const int q0 = qt * 128, k0 = kt * 128;
    const int tid = threadIdx.x, wid = tid >> 5, lane = tid & 31;
    const int wq = wid >> 1, wk = wid & 1;

    // load 4 operand tiles (128 rows x 64 bf16) swizzled
    {
        const __nv_bfloat16* s0 = g_thhi + (size_t)(b * TN + q0) * MIDC;
        const __nv_bfloat16* s1 = g_thlo + (size_t)(b * TN + q0) * MIDC;
        const __nv_bfloat16* s2 = g_phhi + (size_t)(b * TN + k0) * MIDC;
        const __nv_bfloat16* s3 = g_phlo + (size_t)(b * TN + k0) * MIDC;
        const __nv_bfloat16* srcs[4] = { s0, s1, s2, s3 };
#pragma unroll
        for (int it = 0; it < 16; it++) {
            int idx = tid + it * 256;            // 0..4095 16B units
            int mat = idx >> 10, row = (idx >> 3) & 127, u = idx & 7;
            uint4 v = *(const uint4*)(srcs[mat] + (size_t)row * MIDC + u * 8);
            *(uint4*)(smem + mat * 16384 + SWZ128(row * 128 + u * 16)) = v;
        }
    }
    __syncthreads();

    float acc[2][8][4];
#pragma unroll
    for (int i = 0; i < 2; i++)
#pragma unroll
        for (int j = 0; j < 8; j++)
#pragma unroll
            for (int r = 0; r < 4; r++) acc[i][j][r] = 0.f;

    const u32 baseA[2] = { sb, sb + 16384 };
    const u32 baseB[2] = { sb + 32768, sb + 49152 };
    const int pa[3] = { 0, 0, 1 }, pbx[3] = { 0, 1, 0 };
    const int arow = wq * 32 + (lane & 15);
    const int acolx = (lane >> 4) << 4;
    const int brow = wk * 64 + (lane & 7) + ((lane >> 4) << 3);
    const int bcolx = ((lane >> 3) & 1) << 4;

#pragma unroll
    for (int p = 0; p < 3; p++) {
        u32 bA = baseA[pa[p]], bB = baseB[pbx[p]];
#pragma unroll
        for (int ks = 0; ks < 4; ks++) {
            int kb = ks * 32;
            u32 a0[4], a1[4];
            ldsm4(a0, bA + SWZ128((arow) * 128 + kb + acolx));
            ldsm4(a1, bA + SWZ128((arow + 16) * 128 + kb + acolx));
#pragma unroll
            for (int jp = 0; jp < 4; jp++) {
                u32 bb[4];
                ldsm4(bb, bB + SWZ128((brow + jp * 16) * 128 + kb + bcolx));
                mma16816(acc[0][2 * jp],     a0, bb[0], bb[1]);
                mma16816(acc[0][2 * jp + 1], a0, bb[2], bb[3]);
                mma16816(acc[1][2 * jp],     a1, bb[0], bb[1]);
                mma16816(acc[1][2 * jp + 1], a1, bb[2], bb[3]);
            }
        }
    }
    __syncthreads();                             // operands dead

    // exp in registers (fp32), stage E hi, per-column fp32 partial sums
    float* red = (float*)(smem + 33792);         // [4 wq][128 k]
#pragma unroll
    for (int i = 0; i < 2; i++)
#pragma unroll
        for (int j = 0; j < 8; j++)
#pragma unroll
            for (int r = 0; r < 4; r++) acc[i][j][r] = fexp(acc[i][j][r]);

#pragma unroll
    for (int i = 0; i < 2; i++) {
        int qr = wq * 32 + i * 16 + (lane >> 2);
#pragma unroll
        for (int j = 0; j < 8; j++) {
            int kc = wk * 64 + j * 8 + 2 * (lane & 3);
            *(u32*)(smem + qr * 264 + kc * 2)       = pk_hi2(acc[i][j][0], acc[i][j][1]);
            *(u32*)(smem + (qr + 8) * 264 + kc * 2) = pk_hi2(acc[i][j][2], acc[i][j][3]);
        }
    }
#pragma unroll
    for (int j = 0; j < 8; j++) {
        float c0 = (acc[0][j][0] + acc[0][j][2]) + (acc[1][j][0] + acc[1][j][2]);
        float c1 = (acc[0][j][1] + acc[0][j][3]) + (acc[1][j][1] + acc[1][j][3]);
#pragma unroll
        for (int off = 4; off < 32; off <<= 1) {
            c0 += __shfl_xor_sync(0xFFFFFFFFu, c0, off);
            c1 += __shfl_xor_sync(0xFFFFFFFFu, c1, off);
        }
        if (lane < 4) {
            int kc = wk * 64 + j * 8 + 2 * lane;
            red[wq * 128 + kc]     = c0;
            red[wq * 128 + kc + 1] = c1;
        }
    }
    __syncthreads();

    if (tid < 128) {
        float z = (red[tid] + red[128 + tid]) + (red[256 + tid] + red[384 + tid]);
        g_Zp[(qt * BATCH + b) * TN + k0 + tid] = z;
    }

    // coalesced copy-out of E hi (128 rows x 256B)
    for (int row = wid; row < 128; row += 8) {
        uint2 v = *(const uint2*)(smem + row * 264 + lane * 8);
        *(uint2*)&g_Ehi[(size_t)(b * TN + q0 + row) * TN + k0 + lane * 4] = v;
    }
}

// ---------------------------------------------------------------------------
// 3) scalegT (invZ fused): gsT [m][k] = bf16(g[k][m]/Z[k])  (hi only)
// ---------------------------------------------------------------------------
__global__ void __launch_bounds__(256)
scalegT_kernel()
{
    __shared__ float s[64][65];
    __shared__ float siz[64];
    const int k0 = blockIdx.x * 64, b = blockIdx.y;
    const int tid = threadIdx.x;
    if (tid < 64) {
        int idx = b * TN + k0 + tid;
        float z = 0.f;
#pragma unroll
        for (int t = 0; t < 16; t++) z += g_Zp[t * 16384 + idx];
        siz[tid] = 1.0f / z;
    }
    __syncthreads();
#pragma unroll
    for (int t = 0; t < 4; t++) {
        int f4 = tid + t * 256;
        int row = f4 >> 4, c4 = (f4 & 15) << 2;
        float iz = siz[row];
        float4 v = *(const float4*)&g_g[(size_t)(b * TN + k0 + row) * MIDC + c4];
        s[row][c4 + 0] = v.x * iz;  s[row][c4 + 1] = v.y * iz;
        s[row][c4 + 2] = v.z * iz;  s[row][c4 + 3] = v.w * iz;
    }
    __syncthreads();
    int m = tid >> 2, kk0 = (tid & 3) << 4;
    u32 hw[8];
#pragma unroll
    for (int j = 0; j < 8; j++)
        hw[j] = pk_hi2(s[kk0 + 2 * j][m], s[kk0 + 2 * j + 1][m]);
    size_t doff = (size_t)(b * MIDC + m) * TN + k0 + kk0;
    *(uint4*)&g_gsThi[doff]     = make_uint4(hw[0], hw[1], hw[2], hw[3]);
    *(uint4*)&g_gsThi[doff + 8] = make_uint4(hw[4], hw[5], hw[6], hw[7]);
}

// ---------------------------------------------------------------------------
// 4) attn_y: y[q][m] = sum_k Ehi[q][k] * gsT[k][m], single bf16 pass,
//    cp.async double-buffered (2 stages x 16KB: Ehi 8KB + gs 8KB).
// ---------------------------------------------------------------------------
__global__ void __launch_bounds__(256)
attn_y_kernel()
{
    __shared__ __align__(16) char smem[32768];
    const u32 sb = smem_u32(smem);
    const int qt = blockIdx.x, b = blockIdx.y;
    const int q0 = qt * 64;
    const int tid = threadIdx.x, wid = tid >> 5, lane = tid & 31;
    const int wq = wid >> 1, wm = wid & 1;

    float acc[4][4];
#pragma unroll
    for (int j = 0; j < 4; j++)
#pragma unroll
        for (int r = 0; r < 4; r++) acc[j][r] = 0.f;

    const int arow = wq * 16 + (lane & 15);
    const int acolx = (lane >> 4) << 4;
    const int brow = wm * 32 + (lane & 7) + ((lane >> 4) << 3);
    const int bcolx = ((lane >> 3) & 1) << 4;

    auto load_stage = [&](int stage, int kc) {
        u32 base = sb + stage * 16384;
#pragma unroll
        for (int it = 0; it < 2; it++) {
            int idx = tid + it * 256;            // 0..511 16B units
            int row = idx >> 3, u = idx & 7;
            CPA16(base + SWZ128(row * 128 + u * 16),
                  (const void*)&g_Ehi[(size_t)(b * TN + q0 + row) * TN + kc + u * 8]);
        }
#pragma unroll
        for (int it = 0; it < 2; it++) {
            int idx = tid + it * 256;
            int row = idx >> 3, u = idx & 7;
            CPA16(base + 8192 + SWZ128(row * 128 + u * 16),
                  (const void*)&g_gsThi[(size_t)(b * MIDC + row) * TN + kc + u * 8]);
        }
        CPA_COMMIT();
    };

    load_stage(0, 0);
    for (int ch = 0; ch < 32; ch++) {
        if (ch + 1 < 32) {
            load_stage((ch + 1) & 1, (ch + 1) * 64);
            asm volatile("cp.async.wait_group 1;" ::: "memory");
        } else {
            asm volatile("cp.async.wait_group 0;" ::: "memory");
        }
        __syncthreads();
        u32 bA = sb + (ch & 1) * 16384;
        u32 bB = bA + 8192;
#pragma unroll
        for (int ks = 0; ks < 4; ks++) {
            int kb = ks * 32;
            u32 a0[4];
            ldsm4(a0, bA + SWZ128(arow * 128 + kb + acolx));
#pragma unroll
            for (int jp = 0; jp < 2; jp++) {
                u32 bb[4];
                ldsm4(bb, bB + SWZ128((brow + jp * 16) * 128 + kb + bcolx));
                mma16816(acc[2 * jp],     a0, bb[0], bb[1]);
                mma16816(acc[2 * jp + 1], a0, bb[2], bb[3]);
            }
        }
        __syncthreads();
    }

    // epilogue: stage D[64 q][64 m] fp32 (stride 65), write y^T[m][q]
    float* ys = (float*)smem;
    {
        int qr = wq * 16 + (lane >> 2);
#pragma unroll
        for (int j = 0; j < 4; j++) {
            int mc = wm * 32 + j * 8 + 2 * (lane & 3);
            ys[qr * 65 + mc]           = acc[j][0];
            ys[qr * 65 + mc + 1]       = acc[j][1];
            ys[(qr + 8) * 65 + mc]     = acc[j][2];
            ys[(qr + 8) * 65 + mc + 1] = acc[j][3];
        }
    }
    __syncthreads();
    for (int m = wid; m < 64; m += 8) {
        float2 f = make_float2(ys[(lane * 2 + 0) * 65 + m],
                               ys[(lane * 2 + 1) * 65 + m]);
        *(float2*)&g_yT[(size_t)(b * MIDC + m) * TN + q0 + lane * 2] = f;
    }
}

// ---------------------------------------------------------------------------
// 5) refine (FFMA2): refined[q][o] = relu(sum_m yT[m][q]*rw[o][m] + rb[o])
// ---------------------------------------------------------------------------
__global__ void __launch_bounds__(256)
refine_kernel(const float* __restrict__ RW, const float* __restrict__ RB)
{
    __shared__ float As[32 * 128];
    __shared__ float Bs[32 * 128];
    const int b = blockIdx.z;
    const int q0 = blockIdx.x * 128;
    const float* Yb = g_yT + (size_t)b * MIDC * TN;
    const int tid = threadIdx.x;
    const int tx = tid & 15, ty = tid >> 4;

    u64 acc[8][4];
#pragma unroll
    for (int i = 0; i < 8; i++)
#pragma unroll
        for (int j = 0; j < 4; j++) acc[i][j] = 0ULL;

    for (int mt = 0; mt < MIDC; mt += 32) {
#pragma unroll
        for (int t = 0; t < 4; t++) {
            int f4 = tid + t * 256;
            int mm = f4 >> 5, c4 = (f4 & 31) << 2;
            *(float4*)&As[mm * 128 + c4] =
                *(const float4*)&Yb[(size_t)(mt + mm) * TN + q0 + c4];
        }
#pragma unroll
        for (int t = 0; t < 4; t++) {
            int f4 = tid + t * 256;
            int o = f4 >> 3, c4 = (f4 & 7) << 2;
            float4 w4 = *(const float4*)&RW[o * MIDC + mt + c4];
            Bs[(c4 + 0) * 128 + o] = w4.x;  Bs[(c4 + 1) * 128 + o] = w4.y;
            Bs[(c4 + 2) * 128 + o] = w4.z;  Bs[(c4 + 3) * 128 + o] = w4.w;
        }
        __syncthreads();
#pragma unroll 8
        for (int mm = 0; mm < 32; mm++) {
            float4 a0 = *(float4*)&As[mm * 128 + ty * 8];
            float4 a1 = *(float4*)&As[mm * 128 + ty * 8 + 4];
            ulonglong2 b01 = *(ulonglong2*)&Bs[mm * 128 + tx * 8];
            ulonglong2 b23 = *(ulonglong2*)&Bs[mm * 128 + tx * 8 + 4];
            u64 aa[8] = { splat2(a0.x), splat2(a0.y), splat2(a0.z), splat2(a0.w),
                          splat2(a1.x), splat2(a1.y), splat2(a1.z), splat2(a1.w) };
            u64 bb[4] = { b01.x, b01.y, b23.x, b23.y };
#pragma unroll
            for (int i = 0; i < 8; i++)
#pragma unroll
                for (int j = 0; j < 4; j++)
                    acc[i][j] = fma2_(aa[i], bb[j], acc[i][j]);
        }
        __syncthreads();
    }

    float* Rb = g_ref + (size_t)b * TN * OUTC;
    float rbv[8];
#pragma unroll
    for (int j = 0; j < 8; j++) rbv[j] = RB[tx * 8 + j];
#pragma unroll
    for (int i = 0; i < 8; i++) {
        float v[8];
#pragma unroll
        for (int j2 = 0; j2 < 4; j2++) upk2(acc[i][j2], v[2 * j2], v[2 * j2 + 1]);
#pragma unroll
        for (int j = 0; j < 8; j++) v[j] = fmaxf(v[j] + rbv[j], 0.f);
        size_t row = (size_t)(q0 + ty * 8 + i) * OUTC + tx * 8;
        *(float4*)&Rb[row]     = make_float4(v[0], v[1], v[2], v[3]);
        *(float4*)&Rb[row + 4] = make_float4(v[4], v[5], v[6], v[7]);
    }
}

// ---------------------------------------------------------------------------
// 6) out[b,c,t,n] = refined[b][q][o] + pc, q=(n&15)*128+c, o=t*32+(n>>4)
// ---------------------------------------------------------------------------
__global__ void __launch_bounds__(256)
scatter_kernel(const float* __restrict__ pc, float* __restrict__ out)
{
    int i4 = blockIdx.x * 256 + threadIdx.x;     // 524288 float4 tasks
    int idx = i4 << 2;
    int b = idx >> 18;
    int r = idx & 262143;
    int c = r >> 11;
    int t = (r >> 9) & 3;
    int n = r & 511;
    int o = (t << 5) + (n >> 4);
    int qb = ((n & 15) << 7) + c;
    const float* Rb = g_ref + ((size_t)b << 18) + o;
    float4 p = *(const float4*)&pc[idx];
    float4 v;
    v.x = Rb[(qb       ) << 7] + p.x;
    v.y = Rb[(qb +  128) << 7] + p.y;
    v.z = Rb[(qb +  256) << 7] + p.z;
    v.w = Rb[(qb +  384) << 7] + p.w;
    *(float4*)&out[idx] = v;
}

// ---------------------------------------------------------------------------
// Host launcher
// ---------------------------------------------------------------------------
extern "C" void kernel_launch(void* const* d_in, const int* in_sizes, int n_in,
                              void* d_out, int out_size)
{
    const float* pc = (const float*)d_in[0];
    const float* tw = (const float*)d_in[1];
    const float* tb = (const float*)d_in[2];
    const float* pw = (const float*)d_in[3];
    const float* pb = (const float*)d_in[4];
    const float* gw = (const float*)d_in[5];
    const float* gb = (const float*)d_in[6];
    const float* rw = (const float*)d_in[7];
    const float* rb = (const float*)d_in[8];
    float* out = (float*)d_out;

    cudaFuncSetAttribute(scores_kernel,
                         cudaFuncAttributeMaxDynamicSharedMemorySize, SC_SMEM);

    proj_kernel   <<<dim3(16, 3, BATCH), 256>>>(pc, tw, tb, pw, pb, gw, gb);
    scores_kernel <<<dim3(16, 16, BATCH), 256, SC_SMEM>>>();
    scalegT_kernel<<<dim3(32, BATCH), 256>>>();
    attn_y_kernel <<<dim3(32, BATCH), 256>>>();
    refine_kernel <<<dim3(16, 1, BATCH), 256>>>(rw, rb);
    scatter_kernel<<<2048, 256>>>(pc, out);
}

// round 11
// speedup vs baseline: 1.8135x; 1.8135x over previous
#include <cuda_runtime.h>
#include <cuda_bf16.h>

#define BATCH 8
#define CH    128
#define MIDC  64
#define OUTC  128
#define TN    2048

typedef unsigned long long u64;
typedef unsigned int u32;

// ---------------------------------------------------------------------------
// Scratch (device globals; allocation-free per harness rules)
// ---------------------------------------------------------------------------
__device__ __nv_bfloat16 g_thhi[BATCH * TN * MIDC];     // theta hi [b][q][m]
__device__ __nv_bfloat16 g_thlo[BATCH * TN * MIDC];
__device__ __nv_bfloat16 g_phhi[BATCH * TN * MIDC];     // phi hi [b][k][m]
__device__ __nv_bfloat16 g_phlo[BATCH * TN * MIDC];
__device__ float         g_g   [BATCH * TN * MIDC];     // g fp32 [b][k][m]
__device__ __nv_bfloat16 g_Ehi [(size_t)BATCH * TN * TN]; // exp(s) bf16 [b][q][k]
__device__ float g_Zp  [16 * BATCH * TN];
__device__ __nv_bfloat16 g_gsThi[BATCH * MIDC * TN];    // (g*invZ)^T bf16 [b][m][k]
__device__ float g_yT [BATCH * MIDC * TN];              // y^T [b][m][q]
__device__ float g_ref[BATCH * TN * OUTC];              // [b][q][o]

// ---------------------------------------------------------------------------
// PTX helpers (base ISA only)
// ---------------------------------------------------------------------------
__device__ __forceinline__ u32 smem_u32(const void* p) {
    u32 a; asm("{ .reg .u64 t; cvta.to.shared.u64 t, %1; cvt.u32.u64 %0, t; }"
               : "=r"(a) : "l"(p)); return a;
}
#define SWZ128(x) ((x) ^ (((x) >> 3) & 0x70))

__device__ __forceinline__ void ldsm4(u32* r, u32 addr) {
    asm volatile("ldmatrix.sync.aligned.m8n8.x4.shared.b16 {%0,%1,%2,%3}, [%4];"
        : "=r"(r[0]), "=r"(r[1]), "=r"(r[2]), "=r"(r[3]) : "r"(addr));
}
__device__ __forceinline__ void mma16816(float* d, const u32* a, u32 b0, u32 b1) {
    asm volatile("mma.sync.aligned.m16n8k16.row.col.f32.bf16.bf16.f32 "
        "{%0,%1,%2,%3}, {%4,%5,%6,%7}, {%8,%9}, {%0,%1,%2,%3};"
        : "+f"(d[0]), "+f"(d[1]), "+f"(d[2]), "+f"(d[3])
        : "r"(a[0]), "r"(a[1]), "r"(a[2]), "r"(a[3]), "r"(b0), "r"(b1));
}
#define CPA16(dst, src) \
    asm volatile("cp.async.cg.shared.global [%0], [%1], 16;" \
                 :: "r"(dst), "l"(src) : "memory")
#define CPA_COMMIT() asm volatile("cp.async.commit_group;" ::: "memory")

// fp32x2 + fast exp helpers
__device__ __forceinline__ u64 splat2(float x) {
    u64 r; asm("mov.b64 %0,{%1,%1};" : "=l"(r) : "f"(x)); return r;
}
__device__ __forceinline__ u64 fma2_(u64 a, u64 b, u64 c) {
    u64 d; asm("fma.rn.f32x2 %0,%1,%2,%3;" : "=l"(d) : "l"(a), "l"(b), "l"(c)); return d;
}
__device__ __forceinline__ void upk2(u64 p, float& a, float& b) {
    asm("mov.b64 {%0,%1},%2;" : "=f"(a), "=f"(b) : "l"(p));
}
__device__ __forceinline__ float fexp(float x) {
    const float L2E = 1.4426950408889634f;
    float z = fmaf(x, L2E, 12582912.0f);
    float n = z - 12582912.0f;
    float f = fmaf(x, L2E, -n);
    float p =          1.3333558146e-3f;
    p = fmaf(p, f,     9.6181291076e-3f);
    p = fmaf(p, f,     5.5504108665e-2f);
    p = fmaf(p, f,     2.4022650696e-1f);
    p = fmaf(p, f,     6.9314718056e-1f);
    p = fmaf(p, f,     1.0f);
    int ni = __float_as_int(z) - 0x4B400000;
    return p * __int_as_float((ni + 127) << 23);
}
__device__ __forceinline__ u32 pkbf(__nv_bfloat16 a, __nv_bfloat16 b) {
    return (u32)__bfloat16_as_ushort(a) | ((u32)__bfloat16_as_ushort(b) << 16);
}
__device__ __forceinline__ u32 pk_hi2(float x, float y) {
    return pkbf(__float2bfloat16(x), __float2bfloat16(y));
}
__device__ __forceinline__ u32 pk_lo2(float x, float y) {
    __nv_bfloat16 hx = __float2bfloat16(x), hy = __float2bfloat16(y);
    return pkbf(__float2bfloat16(x - __bfloat162float(hx)),
                __float2bfloat16(y - __bfloat162float(hy)));
}

// ---------------------------------------------------------------------------
// 1) Projections: relu(W[64x128]*pc[128x2048]+b).
//    theta,phi -> bf16 hi/lo [tn][64];  g -> fp32 [tn][64].
// ---------------------------------------------------------------------------
__global__ void __launch_bounds__(256)
proj_kernel(const float* __restrict__ pc,
            const float* __restrict__ tw, const float* __restrict__ tb,
            const float* __restrict__ pw, const float* __restrict__ pb,
            const float* __restrict__ gw, const float* __restrict__ gb)
{
    __shared__ float As[32 * 64];
    __shared__ float Bs[32 * 128];
    const int b = blockIdx.z, pj = blockIdx.y;
    const int n0 = blockIdx.x * 128;
    const float *W, *bi;
    if (pj == 0)      { W = tw; bi = tb; }
    else if (pj == 1) { W = pw; bi = pb; }
    else              { W = gw; bi = gb; }
    const float* pcb = pc + (size_t)b * CH * TN;
    const int tid = threadIdx.x;
    const int tx = tid & 15, ty = tid >> 4;

    u64 acc[4][4];
#pragma unroll
    for (int i = 0; i < 4; i++)
#pragma unroll
        for (int j = 0; j < 4; j++) acc[i][j] = 0ULL;

    for (int ct = 0; ct < 128; ct += 32) {
#pragma unroll
        for (int t = 0; t < 2; t++) {
            int f4 = tid + t * 256;
            int m = f4 >> 3, c4 = (f4 & 7) << 2;
            float4 w4 = *(const float4*)&W[m * 128 + ct + c4];
            As[(c4 + 0) * 64 + m] = w4.x;  As[(c4 + 1) * 64 + m] = w4.y;
            As[(c4 + 2) * 64 + m] = w4.z;  As[(c4 + 3) * 64 + m] = w4.w;
        }
#pragma unroll
        for (int t = 0; t < 4; t++) {
            int f4 = tid + t * 256;
            int cc = f4 >> 5, c4 = (f4 & 31) << 2;
            *(float4*)&Bs[cc * 128 + c4] =
                *(const float4*)&pcb[(size_t)(ct + cc) * TN + n0 + c4];
        }
        __syncthreads();
#pragma unroll 8
        for (int cc = 0; cc < 32; cc++) {
            float4 av = *(float4*)&As[cc * 64 + ty * 4];
            ulonglong2 b01 = *(ulonglong2*)&Bs[cc * 128 + tx * 8];
            ulonglong2 b23 = *(ulonglong2*)&Bs[cc * 128 + tx * 8 + 4];
            u64 aa[4] = { splat2(av.x), splat2(av.y), splat2(av.z), splat2(av.w) };
            u64 bb[4] = { b01.x, b01.y, b23.x, b23.y };
#pragma unroll
            for (int i = 0; i < 4; i++)
#pragma unroll
                for (int j = 0; j < 4; j++)
                    acc[i][j] = fma2_(aa[i], bb[j], acc[i][j]);
        }
        __syncthreads();
    }

    float v[4][8];
#pragma unroll
    for (int i = 0; i < 4; i++) {
#pragma unroll
        for (int j2 = 0; j2 < 4; j2++) upk2(acc[i][j2], v[i][2 * j2], v[i][2 * j2 + 1]);
        float bv = bi[ty * 4 + i];
#pragma unroll
        for (int j = 0; j < 8; j++) v[i][j] = fmaxf(v[i][j] + bv, 0.f);
    }
    if (pj < 2) {
        __nv_bfloat16* oh = (pj == 0 ? g_thhi : g_phhi) + (size_t)b * TN * MIDC;
        __nv_bfloat16* ol = (pj == 0 ? g_thlo : g_phlo) + (size_t)b * TN * MIDC;
#pragma unroll
        for (int j = 0; j < 8; j++) {
            int tn = n0 + tx * 8 + j;
            *(uint2*)&oh[(size_t)tn * MIDC + ty * 4] =
                make_uint2(pk_hi2(v[0][j], v[1][j]), pk_hi2(v[2][j], v[3][j]));
            *(uint2*)&ol[(size_t)tn * MIDC + ty * 4] =
                make_uint2(pk_lo2(v[0][j], v[1][j]), pk_lo2(v[2][j], v[3][j]));
        }
    } else {
        float* ob = g_g + (size_t)b * TN * MIDC;
#pragma unroll
        for (int j = 0; j < 8; j++)
            *(float4*)&ob[(size_t)(n0 + tx * 8 + j) * MIDC + ty * 4] =
                make_float4(v[0][j], v[1][j], v[2][j], v[3][j]);
    }
}

// ---------------------------------------------------------------------------
// 2) scores: warp-MMA bf16 3-split with A-fragment reuse, fused exp +
//    register colsum, E hi store. Staging stride 272 B (16-aligned).
// ---------------------------------------------------------------------------
#define SC_SMEM 65536
#define EST 272                                   // staging row stride bytes

__global__ void __launch_bounds__(256)
scores_kernel()
{
    extern __shared__ char smem[];
    const u32 sb = smem_u32(smem);
    const int b = blockIdx.z, qt = blockIdx.y, kt = blockIdx.x;
    const int q0 = qt * 128, k0 = kt * 128;
    const int tid = threadIdx.x, wid = tid >> 5, lane = tid & 31;
    const int wq = wid >> 1, wk = wid & 1;

    // load 4 operand tiles (128 rows x 64 bf16) swizzled
    {
        const __nv_bfloat16* s0 = g_thhi + (size_t)(b * TN + q0) * MIDC;
        const __nv_bfloat16* s1 = g_thlo + (size_t)(b * TN + q0) * MIDC;
        const __nv_bfloat16* s2 = g_phhi + (size_t)(b * TN + k0) * MIDC;
        const __nv_bfloat16* s3 = g_phlo + (size_t)(b * TN + k0) * MIDC;
        const __nv_bfloat16* srcs[4] = { s0, s1, s2, s3 };
#pragma unroll
        for (int it = 0; it < 16; it++) {
            int idx = tid + it * 256;            // 0..4095 16B units
            int mat = idx >> 10, row = (idx >> 3) & 127, u = idx & 7;
            uint4 v = *(const uint4*)(srcs[mat] + (size_t)row * MIDC + u * 8);
            *(uint4*)(smem + mat * 16384 + SWZ128(row * 128 + u * 16)) = v;
        }
    }
    __syncthreads();

    float acc[2][8][4];
#pragma unroll
    for (int i = 0; i < 2; i++)
#pragma unroll
        for (int j = 0; j < 8; j++)
#pragma unroll
            for (int r = 0; r < 4; r++) acc[i][j][r] = 0.f;

    const int arow = wq * 32 + (lane & 15);
    const int acolx = (lane >> 4) << 4;
    const int brow = wk * 64 + (lane & 7) + ((lane >> 4) << 3);
    const int bcolx = ((lane >> 3) & 1) << 4;

#pragma unroll
    for (int ks = 0; ks < 4; ks++) {
        int kb = ks * 32;
        u32 aH0[4], aH1[4], aL0[4], aL1[4];
        ldsm4(aH0, sb         + SWZ128(arow * 128 + kb + acolx));
        ldsm4(aH1, sb         + SWZ128((arow + 16) * 128 + kb + acolx));
        ldsm4(aL0, sb + 16384 + SWZ128(arow * 128 + kb + acolx));
        ldsm4(aL1, sb + 16384 + SWZ128((arow + 16) * 128 + kb + acolx));
#pragma unroll
        for (int jp = 0; jp < 4; jp++) {
            u32 bH[4], bL[4];
            ldsm4(bH, sb + 32768 + SWZ128((brow + jp * 16) * 128 + kb + bcolx));
            ldsm4(bL, sb + 49152 + SWZ128((brow + jp * 16) * 128 + kb + bcolx));
            // hi * hi
            mma16816(acc[0][2 * jp],     aH0, bH[0], bH[1]);
            mma16816(acc[0][2 * jp + 1], aH0, bH[2], bH[3]);
            mma16816(acc[1][2 * jp],     aH1, bH[0], bH[1]);
            mma16816(acc[1][2 * jp + 1], aH1, bH[2], bH[3]);
            // hi * lo
            mma16816(acc[0][2 * jp],     aH0, bL[0], bL[1]);
            mma16816(acc[0][2 * jp + 1], aH0, bL[2], bL[3]);
            mma16816(acc[1][2 * jp],     aH1, bL[0], bL[1]);
            mma16816(acc[1][2 * jp + 1], aH1, bL[2], bL[3]);
            // lo * hi
            mma16816(acc[0][2 * jp],     aL0, bH[0], bH[1]);
            mma16816(acc[0][2 * jp + 1], aL0, bH[2], bH[3]);
            mma16816(acc[1][2 * jp],     aL1, bH[0], bH[1]);
            mma16816(acc[1][2 * jp + 1], aL1, bH[2], bH[3]);
        }
    }
    __syncthreads();                             // operands dead

    // exp in registers (fp32), stage E hi, per-column fp32 partial sums
    float* red = (float*)(smem + 128 * EST);     // 34816: [4 wq][128 k]
#pragma unroll
    for (int i = 0; i < 2; i++)
#pragma unroll
        for (int j = 0; j < 8; j++)
#pragma unroll
            for (int r = 0; r < 4; r++) acc[i][j][r] = fexp(acc[i][j][r]);

#pragma unroll
    for (int i = 0; i < 2; i++) {
        int qr = wq * 32 + i * 16 + (lane >> 2);
#pragma unroll
        for (int j = 0; j < 8; j++) {
            int kc = wk * 64 + j * 8 + 2 * (lane & 3);
            *(u32*)(smem + qr * EST + kc * 2)       = pk_hi2(acc[i][j][0], acc[i][j][1]);
            *(u32*)(smem + (qr + 8) * EST + kc * 2) = pk_hi2(acc[i][j][2], acc[i][j][3]);
        }
    }
#pragma unroll
    for (int j = 0; j < 8; j++) {
        float c0 = (acc[0][j][0] + acc[0][j][2]) + (acc[1][j][0] + acc[1][j][2]);
        float c1 = (acc[0][j][1] + acc[0][j][3]) + (acc[1][j][1] + acc[1][j][3]);
#pragma unroll
        for (int off = 4; off < 32; off <<= 1) {
            c0 += __shfl_xor_sync(0xFFFFFFFFu, c0, off);
            c1 += __shfl_xor_sync(0xFFFFFFFFu, c1, off);
        }
        if (lane < 4) {
            int kc = wk * 64 + j * 8 + 2 * lane;
            red[wq * 128 + kc]     = c0;
            red[wq * 128 + kc + 1] = c1;
        }
    }
    __syncthreads();

    if (tid < 128) {
        float z = (red[tid] + red[128 + tid]) + (red[256 + tid] + red[384 + tid]);
        g_Zp[(qt * BATCH + b) * TN + k0 + tid] = z;
    }

    // coalesced copy-out of E hi: 2 rows per warp per pass, uint4 (16-aligned)
    for (int rp = wid * 2; rp < 128; rp += 16) {
        int row = rp + (lane >> 4);
        int u = lane & 15;
        uint4 v = *(const uint4*)(smem + row * EST + u * 16);
        *(uint4*)&g_Ehi[(size_t)(b * TN + q0 + row) * TN + k0 + u * 8] = v;
    }
}

// ---------------------------------------------------------------------------
// 3) scalegT (invZ fused): gsT [m][k] = bf16(g[k][m]/Z[k])
// ---------------------------------------------------------------------------
__global__ void __launch_bounds__(256)
scalegT_kernel()
{
    __shared__ float s[64][65];
    __shared__ float siz[64];
    const int k0 = blockIdx.x * 64, b = blockIdx.y;
    const int tid = threadIdx.x;
    if (tid < 64) {
        int idx = b * TN + k0 + tid;
        float z = 0.f;
#pragma unroll
        for (int t = 0; t < 16; t++) z += g_Zp[t * 16384 + idx];
        siz[tid] = 1.0f / z;
    }
    __syncthreads();
#pragma unroll
    for (int t = 0; t < 4; t++) {
        int f4 = tid + t * 256;
        int row = f4 >> 4, c4 = (f4 & 15) << 2;
        float iz = siz[row];
        float4 v = *(const float4*)&g_g[(size_t)(b * TN + k0 + row) * MIDC + c4];
        s[row][c4 + 0] = v.x * iz;  s[row][c4 + 1] = v.y * iz;
        s[row][c4 + 2] = v.z * iz;  s[row][c4 + 3] = v.w * iz;
    }
    __syncthreads();
    int m = tid >> 2, kk0 = (tid & 3) << 4;
    u32 hw[8];
#pragma unroll
    for (int j = 0; j < 8; j++)
        hw[j] = pk_hi2(s[kk0 + 2 * j][m], s[kk0 + 2 * j + 1][m]);
    size_t doff = (size_t)(b * MIDC + m) * TN + k0 + kk0;
    *(uint4*)&g_gsThi[doff]     = make_uint4(hw[0], hw[1], hw[2], hw[3]);
    *(uint4*)&g_gsThi[doff + 8] = make_uint4(hw[4], hw[5], hw[6], hw[7]);
}

// ---------------------------------------------------------------------------
// 4) attn_y: y[q][m] = sum_k Ehi[q][k] * gsT[k][m], single bf16 pass,
//    3-stage cp.async pipeline (16KB/stage), ONE barrier per chunk.
// ---------------------------------------------------------------------------
__global__ void __launch_bounds__(256)
attn_y_kernel()
{
    __shared__ __align__(16) char smem[49152];
    const u32 sb = smem_u32(smem);
    const int qt = blockIdx.x, b = blockIdx.y;
    const int q0 = qt * 64;
    const int tid = threadIdx.x, wid = tid >> 5, lane = tid & 31;
    const int wq = wid >> 1, wm = wid & 1;

    float acc[4][4];
#pragma unroll
    for (int j = 0; j < 4; j++)
#pragma unroll
        for (int r = 0; r < 4; r++) acc[j][r] = 0.f;

    const int arow = wq * 16 + (lane & 15);
    const int acolx = (lane >> 4) << 4;
    const int brow = wm * 32 + (lane & 7) + ((lane >> 4) << 3);
    const int bcolx = ((lane >> 3) & 1) << 4;

    auto load_stage = [&](int stage, int kc) {
        u32 base = sb + stage * 16384;
#pragma unroll
        for (int it = 0; it < 2; it++) {
            int idx = tid + it * 256;            // 0..511 16B units
            int row = idx >> 3, u = idx & 7;
            CPA16(base + SWZ128(row * 128 + u * 16),
                  (const void*)&g_Ehi[(size_t)(b * TN + q0 + row) * TN + kc + u * 8]);
        }
#pragma unroll
        for (int it = 0; it < 2; it++) {
            int idx = tid + it * 256;
            int row = idx >> 3, u = idx & 7;
            CPA16(base + 8192 + SWZ128(row * 128 + u * 16),
                  (const void*)&g_gsThi[(size_t)(b * MIDC + row) * TN + kc + u * 8]);
        }
        CPA_COMMIT();
    };

    load_stage(0, 0);
    load_stage(1, 64);
    for (int ch = 0; ch < 32; ch++) {
        if (ch == 31) asm volatile("cp.async.wait_group 0;" ::: "memory");
        else          asm volatile("cp.async.wait_group 1;" ::: "memory");
        __syncthreads();                         // buffer ch visible; MMA(ch-1) done
        if (ch + 2 < 32) load_stage((ch + 2) % 3, (ch + 2) * 64);
        u32 bA = sb + (ch % 3) * 16384;
        u32 bB = bA + 8192;
#pragma unroll
        for (int ks = 0; ks < 4; ks++) {
            int kb = ks * 32;
            u32 a0[4];
            ldsm4(a0, bA + SWZ128(arow * 128 + kb + acolx));
#pragma unroll
            for (int jp = 0; jp < 2; jp++) {
                u32 bb[4];
                ldsm4(bb, bB + SWZ128((brow + jp * 16) * 128 + kb + bcolx));
                mma16816(acc[2 * jp],     a0, bb[0], bb[1]);
                mma16816(acc[2 * jp + 1], a0, bb[2], bb[3]);
            }
        }
    }
    __syncthreads();                             // all MMA done before ys overlay

    // epilogue: stage D[64 q][64 m] fp32 (stride 65), write y^T[m][q]
    float* ys = (float*)smem;
    {
        int qr = wq * 16 + (lane >> 2);
#pragma unroll
        for (int j = 0; j < 4; j++) {
            int mc = wm * 32 + j * 8 + 2 * (lane & 3);
            ys[qr * 65 + mc]           = acc[j][0];
            ys[qr * 65 + mc + 1]       = acc[j][1];
            ys[(qr + 8) * 65 + mc]     = acc[j][2];
            ys[(qr + 8) * 65 + mc + 1] = acc[j][3];
        }
    }
    __syncthreads();
    for (int m = wid; m < 64; m += 8) {
        float2 f = make_float2(ys[(lane * 2 + 0) * 65 + m],
                               ys[(lane * 2 + 1) * 65 + m]);
        *(float2*)&g_yT[(size_t)(b * MIDC + m) * TN + q0 + lane * 2] = f;
    }
}

// ---------------------------------------------------------------------------
// 5) refine (FFMA2): refined[q][o] = relu(sum_m yT[m][q]*rw[o][m] + rb[o])
// ---------------------------------------------------------------------------
__global__ void __launch_bounds__(256)
refine_kernel(const float* __restrict__ RW, const float* __restrict__ RB)
{
    __shared__ float As[32 * 128];
    __shared__ float Bs[32 * 128];
    const int b = blockIdx.z;
    const int q0 = blockIdx.x * 128;
    const float* Yb = g_yT + (size_t)b * MIDC * TN;
    const int tid = threadIdx.x;
    const int tx = tid & 15, ty = tid >> 4;

    u64 acc[8][4];
#pragma unroll
    for (int i = 0; i < 8; i++)
#pragma unroll
        for (int j = 0; j < 4; j++) acc[i][j] = 0ULL;

    for (int mt = 0; mt < MIDC; mt += 32) {
#pragma unroll
        for (int t = 0; t < 4; t++) {
            int f4 = tid + t * 256;
            int mm = f4 >> 5, c4 = (f4 & 31) << 2;
            *(float4*)&As[mm * 128 + c4] =
                *(const float4*)&Yb[(size_t)(mt + mm) * TN + q0 + c4];
        }
#pragma unroll
        for (int t = 0; t < 4; t++) {
            int f4 = tid + t * 256;
            int o = f4 >> 3, c4 = (f4 & 7) << 2;
            float4 w4 = *(const float4*)&RW[o * MIDC + mt + c4];
            Bs[(c4 + 0) * 128 + o] = w4.x;  Bs[(c4 + 1) * 128 + o] = w4.y;
            Bs[(c4 + 2) * 128 + o] = w4.z;  Bs[(c4 + 3) * 128 + o] = w4.w;
        }
        __syncthreads();
#pragma unroll 8
        for (int mm = 0; mm < 32; mm++) {
            float4 a0 = *(float4*)&As[mm * 128 + ty * 8];
            float4 a1 = *(float4*)&As[mm * 128 + ty * 8 + 4];
            ulonglong2 b01 = *(ulonglong2*)&Bs[mm * 128 + tx * 8];
            ulonglong2 b23 = *(ulonglong2*)&Bs[mm * 128 + tx * 8 + 4];
            u64 aa[8] = { splat2(a0.x), splat2(a0.y), splat2(a0.z), splat2(a0.w),
                          splat2(a1.x), splat2(a1.y), splat2(a1.z), splat2(a1.w) };
            u64 bb[4] = { b01.x, b01.y, b23.x, b23.y };
#pragma unroll
            for (int i = 0; i < 8; i++)
#pragma unroll
                for (int j = 0; j < 4; j++)
                    acc[i][j] = fma2_(aa[i], bb[j], acc[i][j]);
        }
        __syncthreads();
    }

    float* Rb = g_ref + (size_t)b * TN * OUTC;
    float rbv[8];
#pragma unroll
    for (int j = 0; j < 8; j++) rbv[j] = RB[tx * 8 + j];
#pragma unroll
    for (int i = 0; i < 8; i++) {
        float v[8];
#pragma unroll
        for (int j2 = 0; j2 < 4; j2++) upk2(acc[i][j2], v[2 * j2], v[2 * j2 + 1]);
#pragma unroll
        for (int j = 0; j < 8; j++) v[j] = fmaxf(v[j] + rbv[j], 0.f);
        size_t row = (size_t)(q0 + ty * 8 + i) * OUTC + tx * 8;
        *(float4*)&Rb[row]     = make_float4(v[0], v[1], v[2], v[3]);
        *(float4*)&Rb[row + 4] = make_float4(v[4], v[5], v[6], v[7]);
    }
}

// ---------------------------------------------------------------------------
// 6) out[b,c,t,n] = refined[b][q][o] + pc, q=(n&15)*128+c, o=t*32+(n>>4)
// ---------------------------------------------------------------------------
__global__ void __launch_bounds__(256)
scatter_kernel(const float* __restrict__ pc, float* __restrict__ out)
{
    int i4 = blockIdx.x * 256 + threadIdx.x;     // 524288 float4 tasks
    int idx = i4 << 2;
    int b = idx >> 18;
    int r = idx & 262143;
    int c = r >> 11;
    int t = (r >> 9) & 3;
    int n = r & 511;
    int o = (t << 5) + (n >> 4);
    int qb = ((n & 15) << 7) + c;
    const float* Rb = g_ref + ((size_t)b << 18) + o;
    float4 p = *(const float4*)&pc[idx];
    float4 v;
    v.x = Rb[(qb       ) << 7] + p.x;
    v.y = Rb[(qb +  128) << 7] + p.y;
    v.z = Rb[(qb +  256) << 7] + p.z;
    v.w = Rb[(qb +  384) << 7] + p.w;
    *(float4*)&out[idx] = v;
}

// ---------------------------------------------------------------------------
// Host launcher
// ---------------------------------------------------------------------------
extern "C" void kernel_launch(void* const* d_in, const int* in_sizes, int n_in,
                              void* d_out, int out_size)
{
    const float* pc = (const float*)d_in[0];
    const float* tw = (const float*)d_in[1];
    const float* tb = (const float*)d_in[2];
    const float* pw = (const float*)d_in[3];
    const float* pb = (const float*)d_in[4];
    const float* gw = (const float*)d_in[5];
    const float* gb = (const float*)d_in[6];
    const float* rw = (const float*)d_in[7];
    const float* rb = (const float*)d_in[8];
    float* out = (float*)d_out;

    cudaFuncSetAttribute(scores_kernel,
                         cudaFuncAttributeMaxDynamicSharedMemorySize, SC_SMEM);

    proj_kernel   <<<dim3(16, 3, BATCH), 256>>>(pc, tw, tb, pw, pb, gw, gb);
    scores_kernel <<<dim3(16, 16, BATCH), 256, SC_SMEM>>>();
    scalegT_kernel<<<dim3(32, BATCH), 256>>>();
    attn_y_kernel <<<dim3(32, BATCH), 256>>>();
    refine_kernel <<<dim3(16, 1, BATCH), 256>>>(rw, rb);
    scatter_kernel<<<2048, 256>>>(pc, out);
}

// round 12
// speedup vs baseline: 1.8427x; 1.0161x over previous
#include <cuda_runtime.h>
#include <cuda_bf16.h>

#define BATCH 8
#define CH    128
#define MIDC  64
#define OUTC  128
#define TN    2048

typedef unsigned long long u64;
typedef unsigned int u32;

// ---------------------------------------------------------------------------
// Scratch (device globals; allocation-free per harness rules)
// ---------------------------------------------------------------------------
__device__ __nv_bfloat16 g_thhi[BATCH * TN * MIDC];     // theta hi [b][q][m]
__device__ __nv_bfloat16 g_thlo[BATCH * TN * MIDC];
__device__ __nv_bfloat16 g_phhi[BATCH * TN * MIDC];     // phi hi [b][k][m]
__device__ __nv_bfloat16 g_phlo[BATCH * TN * MIDC];
__device__ float         g_g   [BATCH * TN * MIDC];     // g fp32 [b][k][m]
__device__ __nv_bfloat16 g_Ehi [(size_t)BATCH * TN * TN]; // exp(s) bf16 [b][q][k]
__device__ float g_Zp  [16 * BATCH * TN];
__device__ __nv_bfloat16 g_gsThi[BATCH * MIDC * TN];    // (g*invZ)^T bf16 [b][m][k]
__device__ float g_yp [2 * BATCH * MIDC * TN];          // y^T split-K partials
__device__ float g_ref[BATCH * TN * OUTC];              // [b][q][o]

// ---------------------------------------------------------------------------
// PTX helpers (base ISA only)
// ---------------------------------------------------------------------------
__device__ __forceinline__ u32 smem_u32(const void* p) {
    u32 a; asm("{ .reg .u64 t; cvta.to.shared.u64 t, %1; cvt.u32.u64 %0, t; }"
               : "=r"(a) : "l"(p)); return a;
}
#define SWZ128(x) ((x) ^ (((x) >> 3) & 0x70))

__device__ __forceinline__ void ldsm4(u32* r, u32 addr) {
    asm volatile("ldmatrix.sync.aligned.m8n8.x4.shared.b16 {%0,%1,%2,%3}, [%4];"
        : "=r"(r[0]), "=r"(r[1]), "=r"(r[2]), "=r"(r[3]) : "r"(addr));
}
__device__ __forceinline__ void mma16816(float* d, const u32* a, u32 b0, u32 b1) {
    asm volatile("mma.sync.aligned.m16n8k16.row.col.f32.bf16.bf16.f32 "
        "{%0,%1,%2,%3}, {%4,%5,%6,%7}, {%8,%9}, {%0,%1,%2,%3};"
        : "+f"(d[0]), "+f"(d[1]), "+f"(d[2]), "+f"(d[3])
        : "r"(a[0]), "r"(a[1]), "r"(a[2]), "r"(a[3]), "r"(b0), "r"(b1));
}
#define CPA16(dst, src) \
    asm volatile("cp.async.cg.shared.global [%0], [%1], 16;" \
                 :: "r"(dst), "l"(src) : "memory")
#define CPA_COMMIT() asm volatile("cp.async.commit_group;" ::: "memory")

// fp32x2 + fast exp helpers
__device__ __forceinline__ u64 splat2(float x) {
    u64 r; asm("mov.b64 %0,{%1,%1};" : "=l"(r) : "f"(x)); return r;
}
__device__ __forceinline__ u64 fma2_(u64 a, u64 b, u64 c) {
    u64 d; asm("fma.rn.f32x2 %0,%1,%2,%3;" : "=l"(d) : "l"(a), "l"(b), "l"(c)); return d;
}
__device__ __forceinline__ void upk2(u64 p, float& a, float& b) {
    asm("mov.b64 {%0,%1},%2;" : "=f"(a), "=f"(b) : "l"(p));
}
__device__ __forceinline__ float fexp(float x) {
    const float L2E = 1.4426950408889634f;
    float z = fmaf(x, L2E, 12582912.0f);
    float n = z - 12582912.0f;
    float f = fmaf(x, L2E, -n);
    float p =          1.3333558146e-3f;
    p = fmaf(p, f,     9.6181291076e-3f);
    p = fmaf(p, f,     5.5504108665e-2f);
    p = fmaf(p, f,     2.4022650696e-1f);
    p = fmaf(p, f,     6.9314718056e-1f);
    p = fmaf(p, f,     1.0f);
    int ni = __float_as_int(z) - 0x4B400000;
    return p * __int_as_float((ni + 127) << 23);
}
__device__ __forceinline__ u32 pkbf(__nv_bfloat16 a, __nv_bfloat16 b) {
    return (u32)__bfloat16_as_ushort(a) | ((u32)__bfloat16_as_ushort(b) << 16);
}
__device__ __forceinline__ u32 pk_hi2(float x, float y) {
    return pkbf(__float2bfloat16(x), __float2bfloat16(y));
}
__device__ __forceinline__ u32 pk_lo2(float x, float y) {
    __nv_bfloat16 hx = __float2bfloat16(x), hy = __float2bfloat16(y);
    return pkbf(__float2bfloat16(x - __bfloat162float(hx)),
                __float2bfloat16(y - __bfloat162float(hy)));
}

// ---------------------------------------------------------------------------
// 1) Projections: relu(W[64x128]*pc[128x2048]+b).
//    theta,phi -> bf16 hi/lo [tn][64];  g -> fp32 [tn][64].
// ---------------------------------------------------------------------------
__global__ void __launch_bounds__(256)
proj_kernel(const float* __restrict__ pc,
            const float* __restrict__ tw, const float* __restrict__ tb,
            const float* __restrict__ pw, const float* __restrict__ pb,
            const float* __restrict__ gw, const float* __restrict__ gb)
{
    __shared__ float As[32 * 64];
    __shared__ float Bs[32 * 128];
    const int b = blockIdx.z, pj = blockIdx.y;
    const int n0 = blockIdx.x * 128;
    const float *W, *bi;
    if (pj == 0)      { W = tw; bi = tb; }
    else if (pj == 1) { W = pw; bi = pb; }
    else              { W = gw; bi = gb; }
    const float* pcb = pc + (size_t)b * CH * TN;
    const int tid = threadIdx.x;
    const int tx = tid & 15, ty = tid >> 4;

    u64 acc[4][4];
#pragma unroll
    for (int i = 0; i < 4; i++)
#pragma unroll
        for (int j = 0; j < 4; j++) acc[i][j] = 0ULL;

    for (int ct = 0; ct < 128; ct += 32) {
#pragma unroll
        for (int t = 0; t < 2; t++) {
            int f4 = tid + t * 256;
            int m = f4 >> 3, c4 = (f4 & 7) << 2;
            float4 w4 = *(const float4*)&W[m * 128 + ct + c4];
            As[(c4 + 0) * 64 + m] = w4.x;  As[(c4 + 1) * 64 + m] = w4.y;
            As[(c4 + 2) * 64 + m] = w4.z;  As[(c4 + 3) * 64 + m] = w4.w;
        }
#pragma unroll
        for (int t = 0; t < 4; t++) {
            int f4 = tid + t * 256;
            int cc = f4 >> 5, c4 = (f4 & 31) << 2;
            *(float4*)&Bs[cc * 128 + c4] =
                *(const float4*)&pcb[(size_t)(ct + cc) * TN + n0 + c4];
        }
        __syncthreads();
#pragma unroll 8
        for (int cc = 0; cc < 32; cc++) {
            float4 av = *(float4*)&As[cc * 64 + ty * 4];
            ulonglong2 b01 = *(ulonglong2*)&Bs[cc * 128 + tx * 8];
            ulonglong2 b23 = *(ulonglong2*)&Bs[cc * 128 + tx * 8 + 4];
            u64 aa[4] = { splat2(av.x), splat2(av.y), splat2(av.z), splat2(av.w) };
            u64 bb[4] = { b01.x, b01.y, b23.x, b23.y };
#pragma unroll
            for (int i = 0; i < 4; i++)
#pragma unroll
                for (int j = 0; j < 4; j++)
                    acc[i][j] = fma2_(aa[i], bb[j], acc[i][j]);
        }
        __syncthreads();
    }

    float v[4][8];
#pragma unroll
    for (int i = 0; i < 4; i++) {
#pragma unroll
        for (int j2 = 0; j2 < 4; j2++) upk2(acc[i][j2], v[i][2 * j2], v[i][2 * j2 + 1]);
        float bv = bi[ty * 4 + i];
#pragma unroll
        for (int j = 0; j < 8; j++) v[i][j] = fmaxf(v[i][j] + bv, 0.f);
    }
    if (pj < 2) {
        __nv_bfloat16* oh = (pj == 0 ? g_thhi : g_phhi) + (size_t)b * TN * MIDC;
        __nv_bfloat16* ol = (pj == 0 ? g_thlo : g_phlo) + (size_t)b * TN * MIDC;
#pragma unroll
        for (int j = 0; j < 8; j++) {
            int tn = n0 + tx * 8 + j;
            *(uint2*)&oh[(size_t)tn * MIDC + ty * 4] =
                make_uint2(pk_hi2(v[0][j], v[1][j]), pk_hi2(v[2][j], v[3][j]));
            *(uint2*)&ol[(size_t)tn * MIDC + ty * 4] =
                make_uint2(pk_lo2(v[0][j], v[1][j]), pk_lo2(v[2][j], v[3][j]));
        }
    } else {
        float* ob = g_g + (size_t)b * TN * MIDC;
#pragma unroll
        for (int j = 0; j < 8; j++)
            *(float4*)&ob[(size_t)(n0 + tx * 8 + j) * MIDC + ty * 4] =
                make_float4(v[0][j], v[1][j], v[2][j], v[3][j]);
    }
}

// ---------------------------------------------------------------------------
// 2) scores: warp-MMA bf16 3-split with A-fragment reuse, fused exp +
//    register colsum, E hi store. cp.async operand loads. Stride 272 B.
// ---------------------------------------------------------------------------
#define SC_SMEM 65536
#define EST 272                                   // staging row stride bytes

__global__ void __launch_bounds__(256)
scores_kernel()
{
    extern __shared__ char smem[];
    const u32 sb = smem_u32(smem);
    const int b = blockIdx.z, qt = blockIdx.y, kt = blockIdx.x;
    const int q0 = qt * 128, k0 = kt * 128;
    const int tid = threadIdx.x, wid = tid >> 5, lane = tid & 31;
    const int wq = wid >> 1, wk = wid & 1;

    // load 4 operand tiles (128 rows x 64 bf16) swizzled, via cp.async
    {
        const __nv_bfloat16* s0 = g_thhi + (size_t)(b * TN + q0) * MIDC;
        const __nv_bfloat16* s1 = g_thlo + (size_t)(b * TN + q0) * MIDC;
        const __nv_bfloat16* s2 = g_phhi + (size_t)(b * TN + k0) * MIDC;
        const __nv_bfloat16* s3 = g_phlo + (size_t)(b * TN + k0) * MIDC;
        const __nv_bfloat16* srcs[4] = { s0, s1, s2, s3 };
#pragma unroll
        for (int it = 0; it < 16; it++) {
            int idx = tid + it * 256;            // 0..4095 16B units
            int mat = idx >> 10, row = (idx >> 3) & 127, u = idx & 7;
            CPA16(sb + mat * 16384 + SWZ128(row * 128 + u * 16),
                  (const void*)(srcs[mat] + (size_t)row * MIDC + u * 8));
        }
        CPA_COMMIT();
        asm volatile("cp.async.wait_group 0;" ::: "memory");
    }
    __syncthreads();

    float acc[2][8][4];
#pragma unroll
    for (int i = 0; i < 2; i++)
#pragma unroll
        for (int j = 0; j < 8; j++)
#pragma unroll
            for (int r = 0; r < 4; r++) acc[i][j][r] = 0.f;

    const int arow = wq * 32 + (lane & 15);
    const int acolx = (lane >> 4) << 4;
    const int brow = wk * 64 + (lane & 7) + ((lane >> 4) << 3);
    const int bcolx = ((lane >> 3) & 1) << 4;

#pragma unroll
    for (int ks = 0; ks < 4; ks++) {
        int kb = ks * 32;
        u32 aH0[4], aH1[4], aL0[4], aL1[4];
        ldsm4(aH0, sb         + SWZ128(arow * 128 + kb + acolx));
        ldsm4(aH1, sb         + SWZ128((arow + 16) * 128 + kb + acolx));
        ldsm4(aL0, sb + 16384 + SWZ128(arow * 128 + kb + acolx));
        ldsm4(aL1, sb + 16384 + SWZ128((arow + 16) * 128 + kb + acolx));
#pragma unroll
        for (int jp = 0; jp < 4; jp++) {
            u32 bH[4], bL[4];
            ldsm4(bH, sb + 32768 + SWZ128((brow + jp * 16) * 128 + kb + bcolx));
            ldsm4(bL, sb + 49152 + SWZ128((brow + jp * 16) * 128 + kb + bcolx));
            // hi * hi
            mma16816(acc[0][2 * jp],     aH0, bH[0], bH[1]);
            mma16816(acc[0][2 * jp + 1], aH0, bH[2], bH[3]);
            mma16816(acc[1][2 * jp],     aH1, bH[0], bH[1]);
            mma16816(acc[1][2 * jp + 1], aH1, bH[2], bH[3]);
            // hi * lo
            mma16816(acc[0][2 * jp],     aH0, bL[0], bL[1]);
            mma16816(acc[0][2 * jp + 1], aH0, bL[2], bL[3]);
            mma16816(acc[1][2 * jp],     aH1, bL[0], bL[1]);
            mma16816(acc[1][2 * jp + 1], aH1, bL[2], bL[3]);
            // lo * hi
            mma16816(acc[0][2 * jp],     aL0, bH[0], bH[1]);
            mma16816(acc[0][2 * jp + 1], aL0, bH[2], bH[3]);
            mma16816(acc[1][2 * jp],     aL1, bH[0], bH[1]);
            mma16816(acc[1][2 * jp + 1], aL1, bH[2], bH[3]);
        }
    }
    __syncthreads();                             // operands dead

    // exp in registers (fp32), stage E hi, per-column fp32 partial sums
    float* red = (float*)(smem + 128 * EST);     // 34816: [4 wq][128 k]
#pragma unroll
    for (int i = 0; i < 2; i++)
#pragma unroll
        for (int j = 0; j < 8; j++)
#pragma unroll
            for (int r = 0; r < 4; r++) acc[i][j][r] = fexp(acc[i][j][r]);

#pragma unroll
    for (int i = 0; i < 2; i++) {
        int qr = wq * 32 + i * 16 + (lane >> 2);
#pragma unroll
        for (int j = 0; j < 8; j++) {
            int kc = wk * 64 + j * 8 + 2 * (lane & 3);
            *(u32*)(smem + qr * EST + kc * 2)       = pk_hi2(acc[i][j][0], acc[i][j][1]);
            *(u32*)(smem + (qr + 8) * EST + kc * 2) = pk_hi2(acc[i][j][2], acc[i][j][3]);
        }
    }
#pragma unroll
    for (int j = 0; j < 8; j++) {
        float c0 = (acc[0][j][0] + acc[0][j][2]) + (acc[1][j][0] + acc[1][j][2]);
        float c1 = (acc[0][j][1] + acc[0][j][3]) + (acc[1][j][1] + acc[1][j][3]);
#pragma unroll
        for (int off = 4; off < 32; off <<= 1) {
            c0 += __shfl_xor_sync(0xFFFFFFFFu, c0, off);
            c1 += __shfl_xor_sync(0xFFFFFFFFu, c1, off);
        }
        if (lane < 4) {
            int kc = wk * 64 + j * 8 + 2 * lane;
            red[wq * 128 + kc]     = c0;
            red[wq * 128 + kc + 1] = c1;
        }
    }
    __syncthreads();

    if (tid < 128) {
        float z = (red[tid] + red[128 + tid]) + (red[256 + tid] + red[384 + tid]);
        g_Zp[(qt * BATCH + b) * TN + k0 + tid] = z;
    }

    // coalesced copy-out of E hi: 2 rows per warp per pass, uint4 (16-aligned)
    for (int rp = wid * 2; rp < 128; rp += 16) {
        int row = rp + (lane >> 4);
        int u = lane & 15;
        uint4 v = *(const uint4*)(smem + row * EST + u * 16);
        *(uint4*)&g_Ehi[(size_t)(b * TN + q0 + row) * TN + k0 + u * 8] = v;
    }
}

// ---------------------------------------------------------------------------
// 3) scalegT (invZ fused): gsT [m][k] = bf16(g[k][m]/Z[k])
// ---------------------------------------------------------------------------
__global__ void __launch_bounds__(256)
scalegT_kernel()
{
    __shared__ float s[64][65];
    __shared__ float siz[64];
    const int k0 = blockIdx.x * 64, b = blockIdx.y;
    const int tid = threadIdx.x;
    if (tid < 64) {
        int idx = b * TN + k0 + tid;
        float z = 0.f;
#pragma unroll
        for (int t = 0; t < 16; t++) z += g_Zp[t * 16384 + idx];
        siz[tid] = 1.0f / z;
    }
    __syncthreads();
#pragma unroll
    for (int t = 0; t < 4; t++) {
        int f4 = tid + t * 256;
        int row = f4 >> 4, c4 = (f4 & 15) << 2;
        float iz = siz[row];
        float4 v = *(const float4*)&g_g[(size_t)(b * TN + k0 + row) * MIDC + c4];
        s[row][c4 + 0] = v.x * iz;  s[row][c4 + 1] = v.y * iz;
        s[row][c4 + 2] = v.z * iz;  s[row][c4 + 3] = v.w * iz;
    }
    __syncthreads();
    int m = tid >> 2, kk0 = (tid & 3) << 4;
    u32 hw[8];
#pragma unroll
    for (int j = 0; j < 8; j++)
        hw[j] = pk_hi2(s[kk0 + 2 * j][m], s[kk0 + 2 * j + 1][m]);
    size_t doff = (size_t)(b * MIDC + m) * TN + k0 + kk0;
    *(uint4*)&g_gsThi[doff]     = make_uint4(hw[0], hw[1], hw[2], hw[3]);
    *(uint4*)&g_gsThi[doff + 8] = make_uint4(hw[4], hw[5], hw[6], hw[7]);
}

// ---------------------------------------------------------------------------
// 4) attn_y: y[q][m] = sum_k Ehi[q][k] * gsT[k][m], split-K=2 (512 blocks =
//    one full resident wave), 3-stage cp.async pipeline, 1 barrier/chunk.
// ---------------------------------------------------------------------------
__global__ void __launch_bounds__(256)
attn_y_kernel()
{
    __shared__ __align__(16) char smem[49152];
    const u32 sb = smem_u32(smem);
    const int sp = blockIdx.x, qt = blockIdx.y, b = blockIdx.z;
    const int q0 = qt * 64;
    const int kbeg = sp * 1024;                  // split-K half
    const int tid = threadIdx.x, wid = tid >> 5, lane = tid & 31;
    const int wq = wid >> 1, wm = wid & 1;

    float acc[4][4];
#pragma unroll
    for (int j = 0; j < 4; j++)
#pragma unroll
        for (int r = 0; r < 4; r++) acc[j][r] = 0.f;

    const int arow = wq * 16 + (lane & 15);
    const int acolx = (lane >> 4) << 4;
    const int brow = wm * 32 + (lane & 7) + ((lane >> 4) << 3);
    const int bcolx = ((lane >> 3) & 1) << 4;

    auto load_stage = [&](int stage, int kc) {
        u32 base = sb + stage * 16384;
#pragma unroll
        for (int it = 0; it < 2; it++) {
            int idx = tid + it * 256;            // 0..511 16B units
            int row = idx >> 3, u = idx & 7;
            CPA16(base + SWZ128(row * 128 + u * 16),
                  (const void*)&g_Ehi[(size_t)(b * TN + q0 + row) * TN + kc + u * 8]);
        }
#pragma unroll
        for (int it = 0; it < 2; it++) {
            int idx = tid + it * 256;
            int row = idx >> 3, u = idx & 7;
            CPA16(base + 8192 + SWZ128(row * 128 + u * 16),
                  (const void*)&g_gsThi[(size_t)(b * MIDC + row) * TN + kc + u * 8]);
        }
        CPA_COMMIT();
    };

    load_stage(0, kbeg);
    load_stage(1, kbeg + 64);
    for (int ch = 0; ch < 16; ch++) {
        if (ch == 15) asm volatile("cp.async.wait_group 0;" ::: "memory");
        else          asm volatile("cp.async.wait_group 1;" ::: "memory");
        __syncthreads();                         // buffer ch visible; MMA(ch-1) done
        if (ch + 2 < 16) load_stage((ch + 2) % 3, kbeg + (ch + 2) * 64);
        u32 bA = sb + (ch % 3) * 16384;
        u32 bB = bA + 8192;
#pragma unroll
        for (int ks = 0; ks < 4; ks++) {
            int kb = ks * 32;
            u32 a0[4];
            ldsm4(a0, bA + SWZ128(arow * 128 + kb + acolx));
#pragma unroll
            for (int jp = 0; jp < 2; jp++) {
                u32 bb[4];
                ldsm4(bb, bB + SWZ128((brow + jp * 16) * 128 + kb + bcolx));
                mma16816(acc[2 * jp],     a0, bb[0], bb[1]);
                mma16816(acc[2 * jp + 1], a0, bb[2], bb[3]);
            }
        }
    }
    __syncthreads();                             // all MMA done before ys overlay

    // epilogue: stage D[64 q][64 m] fp32 (stride 65), write partial y^T[m][q]
    float* ys = (float*)smem;
    {
        int qr = wq * 16 + (lane >> 2);
#pragma unroll
        for (int j = 0; j < 4; j++) {
            int mc = wm * 32 + j * 8 + 2 * (lane & 3);
            ys[qr * 65 + mc]           = acc[j][0];
            ys[qr * 65 + mc + 1]       = acc[j][1];
            ys[(qr + 8) * 65 + mc]     = acc[j][2];
            ys[(qr + 8) * 65 + mc + 1] = acc[j][3];
        }
    }
    __syncthreads();
    float* Yo = g_yp + (size_t)sp * (BATCH * MIDC * TN) + (size_t)b * MIDC * TN;
    for (int m = wid; m < 64; m += 8) {
        float2 f = make_float2(ys[(lane * 2 + 0) * 65 + m],
                               ys[(lane * 2 + 1) * 65 + m]);
        *(float2*)&Yo[(size_t)m * TN + q0 + lane * 2] = f;
    }
}

// ---------------------------------------------------------------------------
// 5) refine (FFMA2): sums split-K partials during A-load.
// ---------------------------------------------------------------------------
__global__ void __launch_bounds__(256)
refine_kernel(const float* __restrict__ RW, const float* __restrict__ RB)
{
    __shared__ float As[32 * 128];
    __shared__ float Bs[32 * 128];
    const int b = blockIdx.z;
    const int q0 = blockIdx.x * 128;
    const float* Y0 = g_yp + (size_t)b * MIDC * TN;
    const float* Y1 = g_yp + (size_t)(BATCH + b) * MIDC * TN;
    const int tid = threadIdx.x;
    const int tx = tid & 15, ty = tid >> 4;

    u64 acc[8][4];
#pragma unroll
    for (int i = 0; i < 8; i++)
#pragma unroll
        for (int j = 0; j < 4; j++) acc[i][j] = 0ULL;

    for (int mt = 0; mt < MIDC; mt += 32) {
#pragma unroll
        for (int t = 0; t < 4; t++) {
            int f4 = tid + t * 256;
            int mm = f4 >> 5, c4 = (f4 & 31) << 2;
            size_t off = (size_t)(mt + mm) * TN + q0 + c4;
            float4 y0 = *(const float4*)&Y0[off];
            float4 y1 = *(const float4*)&Y1[off];
            *(float4*)&As[mm * 128 + c4] = make_float4(
                y0.x + y1.x, y0.y + y1.y, y0.z + y1.z, y0.w + y1.w);
        }
#pragma unroll
        for (int t = 0; t < 4; t++) {
            int f4 = tid + t * 256;
            int o = f4 >> 3, c4 = (f4 & 7) << 2;
            float4 w4 = *(const float4*)&RW[o * MIDC + mt + c4];
            Bs[(c4 + 0) * 128 + o] = w4.x;  Bs[(c4 + 1) * 128 + o] = w4.y;
            Bs[(c4 + 2) * 128 + o] = w4.z;  Bs[(c4 + 3) * 128 + o] = w4.w;
        }
        __syncthreads();
#pragma unroll 8
        for (int mm = 0; mm < 32; mm++) {
            float4 a0 = *(float4*)&As[mm * 128 + ty * 8];
            float4 a1 = *(float4*)&As[mm * 128 + ty * 8 + 4];
            ulonglong2 b01 = *(ulonglong2*)&Bs[mm * 128 + tx * 8];
            ulonglong2 b23 = *(ulonglong2*)&Bs[mm * 128 + tx * 8 + 4];
            u64 aa[8] = { splat2(a0.x), splat2(a0.y), splat2(a0.z), splat2(a0.w),
                          splat2(a1.x), splat2(a1.y), splat2(a1.z), splat2(a1.w) };
            u64 bb[4] = { b01.x, b01.y, b23.x, b23.y };
#pragma unroll
            for (int i = 0; i < 8; i++)
#pragma unroll
                for (int j = 0; j < 4; j++)
                    acc[i][j] = fma2_(aa[i], bb[j], acc[i][j]);
        }
        __syncthreads();
    }

    float* Rb = g_ref + (size_t)b * TN * OUTC;
    float rbv[8];
#pragma unroll
    for (int j = 0; j < 8; j++) rbv[j] = RB[tx * 8 + j];
#pragma unroll
    for (int i = 0; i < 8; i++) {
        float v[8];
#pragma unroll
        for (int j2 = 0; j2 < 4; j2++) upk2(acc[i][j2], v[2 * j2], v[2 * j2 + 1]);
#pragma unroll
        for (int j = 0; j < 8; j++) v[j] = fmaxf(v[j] + rbv[j], 0.f);
        size_t row = (size_t)(q0 + ty * 8 + i) * OUTC + tx * 8;
        *(float4*)&Rb[row]     = make_float4(v[0], v[1], v[2], v[3]);
        *(float4*)&Rb[row + 4] = make_float4(v[4], v[5], v[6], v[7]);
    }
}

// ---------------------------------------------------------------------------
// 6) out[b,c,t,n] = refined[b][q][o] + pc, q=(n&15)*128+c, o=t*32+(n>>4)
// ---------------------------------------------------------------------------
__global__ void __launch_bounds__(256)
scatter_kernel(const float* __restrict__ pc, float* __restrict__ out)
{
    int i4 = blockIdx.x * 256 + threadIdx.x;     // 524288 float4 tasks
    int idx = i4 << 2;
    int b = idx >> 18;
    int r = idx & 262143;
    int c = r >> 11;
    int t = (r >> 9) & 3;
    int n = r & 511;
    int o = (t << 5) + (n >> 4);
    int qb = ((n & 15) << 7) + c;
    const float* Rb = g_ref + ((size_t)b << 18) + o;
    float4 p = *(const float4*)&pc[idx];
    float4 v;
    v.x = Rb[(qb       ) << 7] + p.x;
    v.y = Rb[(qb +  128) << 7] + p.y;
    v.z = Rb[(qb +  256) << 7] + p.z;
    v.w = Rb[(qb +  384) << 7] + p.w;
    *(float4*)&out[idx] = v;
}

// ---------------------------------------------------------------------------
// Host launcher
// ---------------------------------------------------------------------------
extern "C" void kernel_launch(void* const* d_in, const int* in_sizes, int n_in,
                              void* d_out, int out_size)
{
    const float* pc = (const float*)d_in[0];
    const float* tw = (const float*)d_in[1];
    const float* tb = (const float*)d_in[2];
    const float* pw = (const float*)d_in[3];
    const float* pb = (const float*)d_in[4];
    const float* gw = (const float*)d_in[5];
    const float* gb = (const float*)d_in[6];
    const float* rw = (const float*)d_in[7];
    const float* rb = (const float*)d_in[8];
    float* out = (float*)d_out;

    cudaFuncSetAttribute(scores_kernel,
                         cudaFuncAttributeMaxDynamicSharedMemorySize, SC_SMEM);

    proj_kernel   <<<dim3(16, 3, BATCH), 256>>>(pc, tw, tb, pw, pb, gw, gb);
    scores_kernel <<<dim3(16, 16, BATCH), 256, SC_SMEM>>>();
    scalegT_kernel<<<dim3(32, BATCH), 256>>>();
    attn_y_kernel <<<dim3(2, 32, BATCH), 256>>>();
    refine_kernel <<<dim3(16, 1, BATCH), 256>>>(rw, rb);
    scatter_kernel<<<2048, 256>>>(pc, out);
}

// round 13
// speedup vs baseline: 1.9508x; 1.0587x over previous
#include <cuda_runtime.h>
#include <cuda_bf16.h>

#define BATCH 8
#define CH    128
#define MIDC  64
#define OUTC  128
#define TN    2048

typedef unsigned long long u64;
typedef unsigned int u32;

// ---------------------------------------------------------------------------
// Scratch (device globals; allocation-free per harness rules)
// ---------------------------------------------------------------------------
__device__ __nv_bfloat16 g_thhi[BATCH * TN * MIDC];     // theta hi [b][q][m]
__device__ __nv_bfloat16 g_phhi[BATCH * TN * MIDC];     // phi hi [b][k][m]
__device__ __nv_bfloat16 g_phlo[BATCH * TN * MIDC];     // phi lo
__device__ float         g_g   [BATCH * TN * MIDC];     // g fp32 [b][k][m]
__device__ __nv_bfloat16 g_Ehi [(size_t)BATCH * TN * TN]; // exp(s) bf16 [b][q][k]
__device__ float g_Zp  [16 * BATCH * TN];
__device__ __nv_bfloat16 g_gsThi[BATCH * MIDC * TN];    // (g*invZ)^T bf16 [b][m][k]
__device__ float g_yT [BATCH * MIDC * TN];              // y^T [b][m][q]
__device__ float g_ref[BATCH * TN * OUTC];              // [b][q][o]

// ---------------------------------------------------------------------------
// PTX helpers (base ISA only)
// ---------------------------------------------------------------------------
__device__ __forceinline__ u32 smem_u32(const void* p) {
    u32 a; asm("{ .reg .u64 t; cvta.to.shared.u64 t, %1; cvt.u32.u64 %0, t; }"
               : "=r"(a) : "l"(p)); return a;
}
#define SWZ128(x) ((x) ^ (((x) >> 3) & 0x70))

__device__ __forceinline__ void ldsm4(u32* r, u32 addr) {
    asm volatile("ldmatrix.sync.aligned.m8n8.x4.shared.b16 {%0,%1,%2,%3}, [%4];"
        : "=r"(r[0]), "=r"(r[1]), "=r"(r[2]), "=r"(r[3]) : "r"(addr));
}
__device__ __forceinline__ void mma16816(float* d, const u32* a, u32 b0, u32 b1) {
    asm volatile("mma.sync.aligned.m16n8k16.row.col.f32.bf16.bf16.f32 "
        "{%0,%1,%2,%3}, {%4,%5,%6,%7}, {%8,%9}, {%0,%1,%2,%3};"
        : "+f"(d[0]), "+f"(d[1]), "+f"(d[2]), "+f"(d[3])
        : "r"(a[0]), "r"(a[1]), "r"(a[2]), "r"(a[3]), "r"(b0), "r"(b1));
}
#define CPA16(dst, src) \
    asm volatile("cp.async.cg.shared.global [%0], [%1], 16;" \
                 :: "r"(dst), "l"(src) : "memory")
#define CPA_COMMIT() asm volatile("cp.async.commit_group;" ::: "memory")

// fp32x2 + fast exp helpers
__device__ __forceinline__ u64 splat2(float x) {
    u64 r; asm("mov.b64 %0,{%1,%1};" : "=l"(r) : "f"(x)); return r;
}
__device__ __forceinline__ u64 fma2_(u64 a, u64 b, u64 c) {
    u64 d; asm("fma.rn.f32x2 %0,%1,%2,%3;" : "=l"(d) : "l"(a), "l"(b), "l"(c)); return d;
}
__device__ __forceinline__ void upk2(u64 p, float& a, float& b) {
    asm("mov.b64 {%0,%1},%2;" : "=f"(a), "=f"(b) : "l"(p));
}
__device__ __forceinline__ float fexp(float x) {
    const float L2E = 1.4426950408889634f;
    float z = fmaf(x, L2E, 12582912.0f);
    float n = z - 12582912.0f;
    float f = fmaf(x, L2E, -n);
    float p =          1.3333558146e-3f;
    p = fmaf(p, f,     9.6181291076e-3f);
    p = fmaf(p, f,     5.5504108665e-2f);
    p = fmaf(p, f,     2.4022650696e-1f);
    p = fmaf(p, f,     6.9314718056e-1f);
    p = fmaf(p, f,     1.0f);
    int ni = __float_as_int(z) - 0x4B400000;
    return p * __int_as_float((ni + 127) << 23);
}
__device__ __forceinline__ u32 pkbf(__nv_bfloat16 a, __nv_bfloat16 b) {
    return (u32)__bfloat16_as_ushort(a) | ((u32)__bfloat16_as_ushort(b) << 16);
}
__device__ __forceinline__ u32 pk_hi2(float x, float y) {
    return pkbf(__float2bfloat16(x), __float2bfloat16(y));
}
__device__ __forceinline__ u32 pk_lo2(float x, float y) {
    __nv_bfloat16 hx = __float2bfloat16(x), hy = __float2bfloat16(y);
    return pkbf(__float2bfloat16(x - __bfloat162float(hx)),
                __float2bfloat16(y - __bfloat162float(hy)));
}

// ---------------------------------------------------------------------------
// 1) Projections: relu(W[64x128]*pc[128x2048]+b).
//    theta -> bf16 hi [tn][64]; phi -> bf16 hi/lo; g -> fp32.
// ---------------------------------------------------------------------------
__global__ void __launch_bounds__(256)
proj_kernel(const float* __restrict__ pc,
            const float* __restrict__ tw, const float* __restrict__ tb,
            const float* __restrict__ pw, const float* __restrict__ pb,
            const float* __restrict__ gw, const float* __restrict__ gb)
{
    __shared__ float As[32 * 64];
    __shared__ float Bs[32 * 128];
    const int b = blockIdx.z, pj = blockIdx.y;
    const int n0 = blockIdx.x * 128;
    const float *W, *bi;
    if (pj == 0)      { W = tw; bi = tb; }
    else if (pj == 1) { W = pw; bi = pb; }
    else              { W = gw; bi = gb; }
    const float* pcb = pc + (size_t)b * CH * TN;
    const int tid = threadIdx.x;
    const int tx = tid & 15, ty = tid >> 4;

    u64 acc[4][4];
#pragma unroll
    for (int i = 0; i < 4; i++)
#pragma unroll
        for (int j = 0; j < 4; j++) acc[i][j] = 0ULL;

    for (int ct = 0; ct < 128; ct += 32) {
#pragma unroll
        for (int t = 0; t < 2; t++) {
            int f4 = tid + t * 256;
            int m = f4 >> 3, c4 = (f4 & 7) << 2;
            float4 w4 = *(const float4*)&W[m * 128 + ct + c4];
            As[(c4 + 0) * 64 + m] = w4.x;  As[(c4 + 1) * 64 + m] = w4.y;
            As[(c4 + 2) * 64 + m] = w4.z;  As[(c4 + 3) * 64 + m] = w4.w;
        }
#pragma unroll
        for (int t = 0; t < 4; t++) {
            int f4 = tid + t * 256;
            int cc = f4 >> 5, c4 = (f4 & 31) << 2;
            *(float4*)&Bs[cc * 128 + c4] =
                *(const float4*)&pcb[(size_t)(ct + cc) * TN + n0 + c4];
        }
        __syncthreads();
#pragma unroll 8
        for (int cc = 0; cc < 32; cc++) {
            float4 av = *(float4*)&As[cc * 64 + ty * 4];
            ulonglong2 b01 = *(ulonglong2*)&Bs[cc * 128 + tx * 8];
            ulonglong2 b23 = *(ulonglong2*)&Bs[cc * 128 + tx * 8 + 4];
            u64 aa[4] = { splat2(av.x), splat2(av.y), splat2(av.z), splat2(av.w) };
            u64 bb[4] = { b01.x, b01.y, b23.x, b23.y };
#pragma unroll
            for (int i = 0; i < 4; i++)
#pragma unroll
                for (int j = 0; j < 4; j++)
                    acc[i][j] = fma2_(aa[i], bb[j], acc[i][j]);
        }
        __syncthreads();
    }

    float v[4][8];
#pragma unroll
    for (int i = 0; i < 4; i++) {
#pragma unroll
        for (int j2 = 0; j2 < 4; j2++) upk2(acc[i][j2], v[i][2 * j2], v[i][2 * j2 + 1]);
        float bv = bi[ty * 4 + i];
#pragma unroll
        for (int j = 0; j < 8; j++) v[i][j] = fmaxf(v[i][j] + bv, 0.f);
    }
    if (pj == 0) {                               // theta: hi only
        __nv_bfloat16* oh = g_thhi + (size_t)b * TN * MIDC;
#pragma unroll
        for (int j = 0; j < 8; j++) {
            int tn = n0 + tx * 8 + j;
            *(uint2*)&oh[(size_t)tn * MIDC + ty * 4] =
                make_uint2(pk_hi2(v[0][j], v[1][j]), pk_hi2(v[2][j], v[3][j]));
        }
    } else if (pj == 1) {                        // phi: hi + lo
        __nv_bfloat16* oh = g_phhi + (size_t)b * TN * MIDC;
        __nv_bfloat16* ol = g_phlo + (size_t)b * TN * MIDC;
#pragma unroll
        for (int j = 0; j < 8; j++) {
            int tn = n0 + tx * 8 + j;
            *(uint2*)&oh[(size_t)tn * MIDC + ty * 4] =
                make_uint2(pk_hi2(v[0][j], v[1][j]), pk_hi2(v[2][j], v[3][j]));
            *(uint2*)&ol[(size_t)tn * MIDC + ty * 4] =
                make_uint2(pk_lo2(v[0][j], v[1][j]), pk_lo2(v[2][j], v[3][j]));
        }
    } else {
        float* ob = g_g + (size_t)b * TN * MIDC;
#pragma unroll
        for (int j = 0; j < 8; j++)
            *(float4*)&ob[(size_t)(n0 + tx * 8 + j) * MIDC + ty * 4] =
                make_float4(v[0][j], v[1][j], v[2][j], v[3][j]);
    }
}

// ---------------------------------------------------------------------------
// 2) scores: warp-MMA bf16 2-pass (th_hi x ph_hi + th_hi x ph_lo), fused
//    exp + register colsum, E hi store. cp.async operand loads.
// smem: A 0 / BH 16K / BL 32K (16KB each); staging overlays 0..34816,
//       red at 34816.  Total 49152 (dynamic, <= default 48KB limit).
// ---------------------------------------------------------------------------
#define SC_SMEM 49152
#define EST 272                                   // staging row stride bytes

__global__ void __launch_bounds__(256)
scores_kernel()
{
    extern __shared__ char smem[];
    const u32 sb = smem_u32(smem);
    const int b = blockIdx.z, qt = blockIdx.y, kt = blockIdx.x;
    const int q0 = qt * 128, k0 = kt * 128;
    const int tid = threadIdx.x, wid = tid >> 5, lane = tid & 31;
    const int wq = wid >> 1, wk = wid & 1;

    // load 3 operand tiles (128 rows x 64 bf16) swizzled, via cp.async
    {
        const __nv_bfloat16* s0 = g_thhi + (size_t)(b * TN + q0) * MIDC;
        const __nv_bfloat16* s1 = g_phhi + (size_t)(b * TN + k0) * MIDC;
        const __nv_bfloat16* s2 = g_phlo + (size_t)(b * TN + k0) * MIDC;
        const __nv_bfloat16* srcs[3] = { s0, s1, s2 };
#pragma unroll
        for (int it = 0; it < 12; it++) {
            int idx = tid + it * 256;            // 0..3071 16B units
            int mat = idx >> 10, row = (idx >> 3) & 127, u = idx & 7;
            CPA16(sb + mat * 16384 + SWZ128(row * 128 + u * 16),
                  (const void*)(srcs[mat] + (size_t)row * MIDC + u * 8));
        }
        CPA_COMMIT();
        asm volatile("cp.async.wait_group 0;" ::: "memory");
    }
    __syncthreads();

    float acc[2][8][4];
#pragma unroll
    for (int i = 0; i < 2; i++)
#pragma unroll
        for (int j = 0; j < 8; j++)
#pragma unroll
            for (int r = 0; r < 4; r++) acc[i][j][r] = 0.f;

    const int arow = wq * 32 + (lane & 15);
    const int acolx = (lane >> 4) << 4;
    const int brow = wk * 64 + (lane & 7) + ((lane >> 4) << 3);
    const int bcolx = ((lane >> 3) & 1) << 4;

#pragma unroll
    for (int ks = 0; ks < 4; ks++) {
        int kb = ks * 32;
        u32 aH0[4], aH1[4];
        ldsm4(aH0, sb + SWZ128(arow * 128 + kb + acolx));
        ldsm4(aH1, sb + SWZ128((arow + 16) * 128 + kb + acolx));
#pragma unroll
        for (int jp = 0; jp < 4; jp++) {
            u32 bH[4], bL[4];
            ldsm4(bH, sb + 16384 + SWZ128((brow + jp * 16) * 128 + kb + bcolx));
            ldsm4(bL, sb + 32768 + SWZ128((brow + jp * 16) * 128 + kb + bcolx));
            // hi * hi
            mma16816(acc[0][2 * jp],     aH0, bH[0], bH[1]);
            mma16816(acc[0][2 * jp + 1], aH0, bH[2], bH[3]);
            mma16816(acc[1][2 * jp],     aH1, bH[0], bH[1]);
            mma16816(acc[1][2 * jp + 1], aH1, bH[2], bH[3]);
            // hi * lo
            mma16816(acc[0][2 * jp],     aH0, bL[0], bL[1]);
            mma16816(acc[0][2 * jp + 1], aH0, bL[2], bL[3]);
            mma16816(acc[1][2 * jp],     aH1, bL[0], bL[1]);
            mma16816(acc[1][2 * jp + 1], aH1, bL[2], bL[3]);
        }
    }
    __syncthreads();                             // operands dead

    // exp in registers (fp32), stage E hi, per-column fp32 partial sums
    float* red = (float*)(smem + 128 * EST);     // 34816: [4 wq][128 k]
#pragma unroll
    for (int i = 0; i < 2; i++)
#pragma unroll
        for (int j = 0; j < 8; j++)
#pragma unroll
            for (int r = 0; r < 4; r++) acc[i][j][r] = fexp(acc[i][j][r]);

#pragma unroll
    for (int i = 0; i < 2; i++) {
        int qr = wq * 32 + i * 16 + (lane >> 2);
#pragma unroll
        for (int j = 0; j < 8; j++) {
            int kc = wk * 64 + j * 8 + 2 * (lane & 3);
            *(u32*)(smem + qr * EST + kc * 2)       = pk_hi2(acc[i][j][0], acc[i][j][1]);
            *(u32*)(smem + (qr + 8) * EST + kc * 2) = pk_hi2(acc[i][j][2], acc[i][j][3]);
        }
    }
#pragma unroll
    for (int j = 0; j < 8; j++) {
        float c0 = (acc[0][j][0] + acc[0][j][2]) + (acc[1][j][0] + acc[1][j][2]);
        float c1 = (acc[0][j][1] + acc[0][j][3]) + (acc[1][j][1] + acc[1][j][3]);
#pragma unroll
        for (int off = 4; off < 32; off <<= 1) {
            c0 += __shfl_xor_sync(0xFFFFFFFFu, c0, off);
            c1 += __shfl_xor_sync(0xFFFFFFFFu, c1, off);
        }
        if (lane < 4) {
            int kc = wk * 64 + j * 8 + 2 * lane;
            red[wq * 128 + kc]     = c0;
            red[wq * 128 + kc + 1] = c1;
        }
    }
    __syncthreads();

    if (tid < 128) {
        float z = (red[tid] + red[128 + tid]) + (red[256 + tid] + red[384 + tid]);
        g_Zp[(qt * BATCH + b) * TN + k0 + tid] = z;
    }

    // coalesced copy-out of E hi: 2 rows per warp per pass, uint4 (16-aligned)
    for (int rp = wid * 2; rp < 128; rp += 16) {
        int row = rp + (lane >> 4);
        int u = lane & 15;
        uint4 v = *(const uint4*)(smem + row * EST + u * 16);
        *(uint4*)&g_Ehi[(size_t)(b * TN + q0 + row) * TN + k0 + u * 8] = v;
    }
}

// ---------------------------------------------------------------------------
// 3) scalegT (invZ fused): gsT [m][k] = bf16(g[k][m]/Z[k])
// ---------------------------------------------------------------------------
__global__ void __launch_bounds__(256)
scalegT_kernel()
{
    __shared__ float s[64][65];
    __shared__ float siz[64];
    const int k0 = blockIdx.x * 64, b = blockIdx.y;
    const int tid = threadIdx.x;
    if (tid < 64) {
        int idx = b * TN + k0 + tid;
        float z = 0.f;
#pragma unroll
        for (int t = 0; t < 16; t++) z += g_Zp[t * 16384 + idx];
        siz[tid] = 1.0f / z;
    }
    __syncthreads();
#pragma unroll
    for (int t = 0; t < 4; t++) {
        int f4 = tid + t * 256;
        int row = f4 >> 4, c4 = (f4 & 15) << 2;
        float iz = siz[row];
        float4 v = *(const float4*)&g_g[(size_t)(b * TN + k0 + row) * MIDC + c4];
        s[row][c4 + 0] = v.x * iz;  s[row][c4 + 1] = v.y * iz;
        s[row][c4 + 2] = v.z * iz;  s[row][c4 + 3] = v.w * iz;
    }
    __syncthreads();
    int m = tid >> 2, kk0 = (tid & 3) << 4;
    u32 hw[8];
#pragma unroll
    for (int j = 0; j < 8; j++)
        hw[j] = pk_hi2(s[kk0 + 2 * j][m], s[kk0 + 2 * j + 1][m]);
    size_t doff = (size_t)(b * MIDC + m) * TN + k0 + kk0;
    *(uint4*)&g_gsThi[doff]     = make_uint4(hw[0], hw[1], hw[2], hw[3]);
    *(uint4*)&g_gsThi[doff + 8] = make_uint4(hw[4], hw[5], hw[6], hw[7]);
}

// ---------------------------------------------------------------------------
// 4) attn_y: y[q][m] = sum_k Ehi[q][k] * gsT[k][m], single bf16 pass,
//    3-stage cp.async pipeline, 1 barrier/chunk.  (R11 form, no split-K.)
// ---------------------------------------------------------------------------
__global__ void __launch_bounds__(256)
attn_y_kernel()
{
    __shared__ __align__(16) char smem[49152];
    const u32 sb = smem_u32(smem);
    const int qt = blockIdx.x, b = blockIdx.y;
    const int q0 = qt * 64;
    const int tid = threadIdx.x, wid = tid >> 5, lane = tid & 31;
    const int wq = wid >> 1, wm = wid & 1;

    float acc[4][4];
#pragma unroll
    for (int j = 0; j < 4; j++)
#pragma unroll
        for (int r = 0; r < 4; r++) acc[j][r] = 0.f;

    const int arow = wq * 16 + (lane & 15);
    const int acolx = (lane >> 4) << 4;
    const int brow = wm * 32 + (lane & 7) + ((lane >> 4) << 3);
    const int bcolx = ((lane >> 3) & 1) << 4;

    auto load_stage = [&](int stage, int kc) {
        u32 base = sb + stage * 16384;
#pragma unroll
        for (int it = 0; it < 2; it++) {
            int idx = tid + it * 256;            // 0..511 16B units
            int row = idx >> 3, u = idx & 7;
            CPA16(base + SWZ128(row * 128 + u * 16),
                  (const void*)&g_Ehi[(size_t)(b * TN + q0 + row) * TN + kc + u * 8]);
        }
#pragma unroll
        for (int it = 0; it < 2; it++) {
            int idx = tid + it * 256;
            int row = idx >> 3, u = idx & 7;
            CPA16(base + 8192 + SWZ128(row * 128 + u * 16),
                  (const void*)&g_gsThi[(size_t)(b * MIDC + row) * TN + kc + u * 8]);
        }
        CPA_COMMIT();
    };

    load_stage(0, 0);
    load_stage(1, 64);
    for (int ch = 0; ch < 32; ch++) {
        if (ch == 31) asm volatile("cp.async.wait_group 0;" ::: "memory");
        else          asm volatile("cp.async.wait_group 1;" ::: "memory");
        __syncthreads();                         // buffer ch visible; MMA(ch-1) done
        if (ch + 2 < 32) load_stage((ch + 2) % 3, (ch + 2) * 64);
        u32 bA = sb + (ch % 3) * 16384;
        u32 bB = bA + 8192;
#pragma unroll
        for (int ks = 0; ks < 4; ks++) {
            int kb = ks * 32;
            u32 a0[4];
            ldsm4(a0, bA + SWZ128(arow * 128 + kb + acolx));
#pragma unroll
            for (int jp = 0; jp < 2; jp++) {
                u32 bb[4];
                ldsm4(bb, bB + SWZ128((brow + jp * 16) * 128 + kb + bcolx));
                mma16816(acc[2 * jp],     a0, bb[0], bb[1]);
                mma16816(acc[2 * jp + 1], a0, bb[2], bb[3]);
            }
        }
    }
    __syncthreads();                             // all MMA done before ys overlay

    // epilogue: stage D[64 q][64 m] fp32 (stride 65), write y^T[m][q]
    float* ys = (float*)smem;
    {
        int qr = wq * 16 + (lane >> 2);
#pragma unroll
        for (int j = 0; j < 4; j++) {
            int mc = wm * 32 + j * 8 + 2 * (lane & 3);
            ys[qr * 65 + mc]           = acc[j][0];
            ys[qr * 65 + mc + 1]       = acc[j][1];
            ys[(qr + 8) * 65 + mc]     = acc[j][2];
            ys[(qr + 8) * 65 + mc + 1] = acc[j][3];
        }
    }
    __syncthreads();
    for (int m = wid; m < 64; m += 8) {
        float2 f = make_float2(ys[(lane * 2 + 0) * 65 + m],
                               ys[(lane * 2 + 1) * 65 + m]);
        *(float2*)&g_yT[(size_t)(b * MIDC + m) * TN + q0 + lane * 2] = f;
    }
}

// ---------------------------------------------------------------------------
// 5) refine (FFMA2): refined[q][o] = relu(sum_m yT[m][q]*rw[o][m] + rb[o])
// ---------------------------------------------------------------------------
__global__ void __launch_bounds__(256)
refine_kernel(const float* __restrict__ RW, const float* __restrict__ RB)
{
    __shared__ float As[32 * 128];
    __shared__ float Bs[32 * 128];
    const int b = blockIdx.z;
    const int q0 = blockIdx.x * 128;
    const float* Yb = g_yT + (size_t)b * MIDC * TN;
    const int tid = threadIdx.x;
    const int tx = tid & 15, ty = tid >> 4;

    u64 acc[8][4];
#pragma unroll
    for (int i = 0; i < 8; i++)
#pragma unroll
        for (int j = 0; j < 4; j++) acc[i][j] = 0ULL;

    for (int mt = 0; mt < MIDC; mt += 32) {
#pragma unroll
        for (int t = 0; t < 4; t++) {
            int f4 = tid + t * 256;
            int mm = f4 >> 5, c4 = (f4 & 31) << 2;
            *(float4*)&As[mm * 128 + c4] =
                *(const float4*)&Yb[(size_t)(mt + mm) * TN + q0 + c4];
        }
#pragma unroll
        for (int t = 0; t < 4; t++) {
            int f4 = tid + t * 256;
            int o = f4 >> 3, c4 = (f4 & 7) << 2;
            float4 w4 = *(const float4*)&RW[o * MIDC + mt + c4];
            Bs[(c4 + 0) * 128 + o] = w4.x;  Bs[(c4 + 1) * 128 + o] = w4.y;
            Bs[(c4 + 2) * 128 + o] = w4.z;  Bs[(c4 + 3) * 128 + o] = w4.w;
        }
        __syncthreads();
#pragma unroll 8
        for (int mm = 0; mm < 32; mm++) {
            float4 a0 = *(float4*)&As[mm * 128 + ty * 8];
            float4 a1 = *(float4*)&As[mm * 128 + ty * 8 + 4];
            ulonglong2 b01 = *(ulonglong2*)&Bs[mm * 128 + tx * 8];
            ulonglong2 b23 = *(ulonglong2*)&Bs[mm * 128 + tx * 8 + 4];
            u64 aa[8] = { splat2(a0.x), splat2(a0.y), splat2(a0.z), splat2(a0.w),
                          splat2(a1.x), splat2(a1.y), splat2(a1.z), splat2(a1.w) };
            u64 bb[4] = { b01.x, b01.y, b23.x, b23.y };
#pragma unroll
            for (int i = 0; i < 8; i++)
#pragma unroll
                for (int j = 0; j < 4; j++)
                    acc[i][j] = fma2_(aa[i], bb[j], acc[i][j]);
        }
        __syncthreads();
    }

    float* Rb = g_ref + (size_t)b * TN * OUTC;
    float rbv[8];
#pragma unroll
    for (int j = 0; j < 8; j++) rbv[j] = RB[tx * 8 + j];
#pragma unroll
    for (int i = 0; i < 8; i++) {
        float v[8];
#pragma unroll
        for (int j2 = 0; j2 < 4; j2++) upk2(acc[i][j2], v[2 * j2], v[2 * j2 + 1]);
#pragma unroll
        for (int j = 0; j < 8; j++) v[j] = fmaxf(v[j] + rbv[j], 0.f);
        size_t row = (size_t)(q0 + ty * 8 + i) * OUTC + tx * 8;
        *(float4*)&Rb[row]     = make_float4(v[0], v[1], v[2], v[3]);
        *(float4*)&Rb[row + 4] = make_float4(v[4], v[5], v[6], v[7]);
    }
}

// ---------------------------------------------------------------------------
// 6) out[b,c,t,n] = refined[b][q][o] + pc, q=(n&15)*128+c, o=t*32+(n>>4)
// ---------------------------------------------------------------------------
__global__ void __launch_bounds__(256)
scatter_kernel(const float* __restrict__ pc, float* __restrict__ out)
{
    int i4 = blockIdx.x * 256 + threadIdx.x;     // 524288 float4 tasks
    int idx = i4 << 2;
    int b = idx >> 18;
    int r = idx & 262143;
    int c = r >> 11;
    int t = (r >> 9) & 3;
    int n = r & 511;
    int o = (t << 5) + (n >> 4);
    int qb = ((n & 15) << 7) + c;
    const float* Rb = g_ref + ((size_t)b << 18) + o;
    float4 p = *(const float4*)&pc[idx];
    float4 v;
    v.x = Rb[(qb       ) << 7] + p.x;
    v.y = Rb[(qb +  128) << 7] + p.y;
    v.z = Rb[(qb +  256) << 7] + p.z;
    v.w = Rb[(qb +  384) << 7] + p.w;
    *(float4*)&out[idx] = v;
}

// ---------------------------------------------------------------------------
// Host launcher
// ---------------------------------------------------------------------------
extern "C" void kernel_launch(void* const* d_in, const int* in_sizes, int n_in,
                              void* d_out, int out_size)
{
    const float* pc = (const float*)d_in[0];
    const float* tw = (const float*)d_in[1];
    const float* tb = (const float*)d_in[2];
    const float* pw = (const float*)d_in[3];
    const float* pb = (const float*)d_in[4];
    const float* gw = (const float*)d_in[5];
    const float* gb = (const float*)d_in[6];
    const float* rw = (const float*)d_in[7];
    const float* rb = (const float*)d_in[8];
    float* out = (float*)d_out;

    proj_kernel   <<<dim3(16, 3, BATCH), 256>>>(pc, tw, tb, pw, pb, gw, gb);
    scores_kernel <<<dim3(16, 16, BATCH), 256, SC_SMEM>>>();
    scalegT_kernel<<<dim3(32, BATCH), 256>>>();
    attn_y_kernel <<<dim3(32, BATCH), 256>>>();
    refine_kernel <<<dim3(16, 1, BATCH), 256>>>(rw, rb);
    scatter_kernel<<<2048, 256>>>(pc, out);
}

// round 14
// speedup vs baseline: 1.9892x; 1.0197x over previous
#include <cuda_runtime.h>
#include <cuda_bf16.h>

#define BATCH 8
#define CH    128
#define MIDC  64
#define OUTC  128
#define TN    2048

typedef unsigned long long u64;
typedef unsigned int u32;

// ---------------------------------------------------------------------------
// Scratch (device globals; allocation-free per harness rules)
// ---------------------------------------------------------------------------
__device__ __nv_bfloat16 g_thhi[BATCH * TN * MIDC];     // theta hi [b][q][m]
__device__ __nv_bfloat16 g_phhi[BATCH * TN * MIDC];     // phi hi [b][k][m]
__device__ __nv_bfloat16 g_phlo[BATCH * TN * MIDC];     // phi lo
__device__ float         g_g   [BATCH * TN * MIDC];     // g fp32 [b][k][m]
__device__ __nv_bfloat16 g_Ehi [(size_t)BATCH * TN * TN]; // exp(s) bf16 [b][q][k]
__device__ float g_Zp  [16 * BATCH * TN];
__device__ __nv_bfloat16 g_gsThi[BATCH * MIDC * TN];    // (g*invZ)^T bf16 [b][m][k]
__device__ float g_yT [BATCH * MIDC * TN];              // y^T [b][m][q]
__device__ float g_ref[BATCH * TN * OUTC];              // [b][q][o]

// ---------------------------------------------------------------------------
// PTX helpers (base ISA only)
// ---------------------------------------------------------------------------
__device__ __forceinline__ u32 smem_u32(const void* p) {
    u32 a; asm("{ .reg .u64 t; cvta.to.shared.u64 t, %1; cvt.u32.u64 %0, t; }"
               : "=r"(a) : "l"(p)); return a;
}
#define SWZ128(x) ((x) ^ (((x) >> 3) & 0x70))

__device__ __forceinline__ void ldsm4(u32* r, u32 addr) {
    asm volatile("ldmatrix.sync.aligned.m8n8.x4.shared.b16 {%0,%1,%2,%3}, [%4];"
        : "=r"(r[0]), "=r"(r[1]), "=r"(r[2]), "=r"(r[3]) : "r"(addr));
}
__device__ __forceinline__ void mma16816(float* d, const u32* a, u32 b0, u32 b1) {
    asm volatile("mma.sync.aligned.m16n8k16.row.col.f32.bf16.bf16.f32 "
        "{%0,%1,%2,%3}, {%4,%5,%6,%7}, {%8,%9}, {%0,%1,%2,%3};"
        : "+f"(d[0]), "+f"(d[1]), "+f"(d[2]), "+f"(d[3])
        : "r"(a[0]), "r"(a[1]), "r"(a[2]), "r"(a[3]), "r"(b0), "r"(b1));
}
#define CPA16(dst, src) \
    asm volatile("cp.async.cg.shared.global [%0], [%1], 16;" \
                 :: "r"(dst), "l"(src) : "memory")
#define CPA_COMMIT() asm volatile("cp.async.commit_group;" ::: "memory")

// fp32x2 + fast exp helpers
__device__ __forceinline__ u64 splat2(float x) {
    u64 r; asm("mov.b64 %0,{%1,%1};" : "=l"(r) : "f"(x)); return r;
}
__device__ __forceinline__ u64 fma2_(u64 a, u64 b, u64 c) {
    u64 d; asm("fma.rn.f32x2 %0,%1,%2,%3;" : "=l"(d) : "l"(a), "l"(b), "l"(c)); return d;
}
__device__ __forceinline__ void upk2(u64 p, float& a, float& b) {
    asm("mov.b64 {%0,%1},%2;" : "=f"(a), "=f"(b) : "l"(p));
}
__device__ __forceinline__ float fexp(float x) {
    const float L2E = 1.4426950408889634f;
    float z = fmaf(x, L2E, 12582912.0f);
    float n = z - 12582912.0f;
    float f = fmaf(x, L2E, -n);
    float p =          1.3333558146e-3f;
    p = fmaf(p, f,     9.6181291076e-3f);
    p = fmaf(p, f,     5.5504108665e-2f);
    p = fmaf(p, f,     2.4022650696e-1f);
    p = fmaf(p, f,     6.9314718056e-1f);
    p = fmaf(p, f,     1.0f);
    int ni = __float_as_int(z) - 0x4B400000;
    return p * __int_as_float((ni + 127) << 23);
}
__device__ __forceinline__ u32 pkbf(__nv_bfloat16 a, __nv_bfloat16 b) {
    return (u32)__bfloat16_as_ushort(a) | ((u32)__bfloat16_as_ushort(b) << 16);
}
__device__ __forceinline__ u32 pk_hi2(float x, float y) {
    return pkbf(__float2bfloat16(x), __float2bfloat16(y));
}
__device__ __forceinline__ u32 pk_lo2(float x, float y) {
    __nv_bfloat16 hx = __float2bfloat16(x), hy = __float2bfloat16(y);
    return pkbf(__float2bfloat16(x - __bfloat162float(hx)),
                __float2bfloat16(y - __bfloat162float(hy)));
}

// ---------------------------------------------------------------------------
// 1) Projections: relu(W[64x128]*pc[128x2048]+b).
//    theta -> bf16 hi [tn][64]; phi -> bf16 hi/lo; g -> fp32.
// ---------------------------------------------------------------------------
__global__ void __launch_bounds__(256)
proj_kernel(const float* __restrict__ pc,
            const float* __restrict__ tw, const float* __restrict__ tb,
            const float* __restrict__ pw, const float* __restrict__ pb,
            const float* __restrict__ gw, const float* __restrict__ gb)
{
    __shared__ float As[32 * 64];
    __shared__ float Bs[32 * 128];
    const int b = blockIdx.z, pj = blockIdx.y;
    const int n0 = blockIdx.x * 128;
    const float *W, *bi;
    if (pj == 0)      { W = tw; bi = tb; }
    else if (pj == 1) { W = pw; bi = pb; }
    else              { W = gw; bi = gb; }
    const float* pcb = pc + (size_t)b * CH * TN;
    const int tid = threadIdx.x;
    const int tx = tid & 15, ty = tid >> 4;

    u64 acc[4][4];
#pragma unroll
    for (int i = 0; i < 4; i++)
#pragma unroll
        for (int j = 0; j < 4; j++) acc[i][j] = 0ULL;

    for (int ct = 0; ct < 128; ct += 32) {
#pragma unroll
        for (int t = 0; t < 2; t++) {
            int f4 = tid + t * 256;
            int m = f4 >> 3, c4 = (f4 & 7) << 2;
            float4 w4 = *(const float4*)&W[m * 128 + ct + c4];
            As[(c4 + 0) * 64 + m] = w4.x;  As[(c4 + 1) * 64 + m] = w4.y;
            As[(c4 + 2) * 64 + m] = w4.z;  As[(c4 + 3) * 64 + m] = w4.w;
        }
#pragma unroll
        for (int t = 0; t < 4; t++) {
            int f4 = tid + t * 256;
            int cc = f4 >> 5, c4 = (f4 & 31) << 2;
            *(float4*)&Bs[cc * 128 + c4] =
                *(const float4*)&pcb[(size_t)(ct + cc) * TN + n0 + c4];
        }
        __syncthreads();
#pragma unroll 8
        for (int cc = 0; cc < 32; cc++) {
            float4 av = *(float4*)&As[cc * 64 + ty * 4];
            ulonglong2 b01 = *(ulonglong2*)&Bs[cc * 128 + tx * 8];
            ulonglong2 b23 = *(ulonglong2*)&Bs[cc * 128 + tx * 8 + 4];
            u64 aa[4] = { splat2(av.x), splat2(av.y), splat2(av.z), splat2(av.w) };
            u64 bb[4] = { b01.x, b01.y, b23.x, b23.y };
#pragma unroll
            for (int i = 0; i < 4; i++)
#pragma unroll
                for (int j = 0; j < 4; j++)
                    acc[i][j] = fma2_(aa[i], bb[j], acc[i][j]);
        }
        __syncthreads();
    }

    float v[4][8];
#pragma unroll
    for (int i = 0; i < 4; i++) {
#pragma unroll
        for (int j2 = 0; j2 < 4; j2++) upk2(acc[i][j2], v[i][2 * j2], v[i][2 * j2 + 1]);
        float bv = bi[ty * 4 + i];
#pragma unroll
        for (int j = 0; j < 8; j++) v[i][j] = fmaxf(v[i][j] + bv, 0.f);
    }
    if (pj == 0) {                               // theta: hi only
        __nv_bfloat16* oh = g_thhi + (size_t)b * TN * MIDC;
#pragma unroll
        for (int j = 0; j < 8; j++) {
            int tn = n0 + tx * 8 + j;
            *(uint2*)&oh[(size_t)tn * MIDC + ty * 4] =
                make_uint2(pk_hi2(v[0][j], v[1][j]), pk_hi2(v[2][j], v[3][j]));
        }
    } else if (pj == 1) {                        // phi: hi + lo
        __nv_bfloat16* oh = g_phhi + (size_t)b * TN * MIDC;
        __nv_bfloat16* ol = g_phlo + (size_t)b * TN * MIDC;
#pragma unroll
        for (int j = 0; j < 8; j++) {
            int tn = n0 + tx * 8 + j;
            *(uint2*)&oh[(size_t)tn * MIDC + ty * 4] =
                make_uint2(pk_hi2(v[0][j], v[1][j]), pk_hi2(v[2][j], v[3][j]));
            *(uint2*)&ol[(size_t)tn * MIDC + ty * 4] =
                make_uint2(pk_lo2(v[0][j], v[1][j]), pk_lo2(v[2][j], v[3][j]));
        }
    } else {
        float* ob = g_g + (size_t)b * TN * MIDC;
#pragma unroll
        for (int j = 0; j < 8; j++)
            *(float4*)&ob[(size_t)(n0 + tx * 8 + j) * MIDC + ty * 4] =
                make_float4(v[0][j], v[1][j], v[2][j], v[3][j]);
    }
}

// ---------------------------------------------------------------------------
// 2) scores: warp-MMA bf16 2-pass (th_hi x ph_hi + th_hi x ph_lo), fused
//    exp + register colsum, E hi store. cp.async operand loads.
// ---------------------------------------------------------------------------
#define SC_SMEM 49152
#define EST 272                                   // staging row stride bytes

__global__ void __launch_bounds__(256)
scores_kernel()
{
    extern __shared__ char smem[];
    const u32 sb = smem_u32(smem);
    const int b = blockIdx.z, qt = blockIdx.y, kt = blockIdx.x;
    const int q0 = qt * 128, k0 = kt * 128;
    const int tid = threadIdx.x, wid = tid >> 5, lane = tid & 31;
    const int wq = wid >> 1, wk = wid & 1;

    // load 3 operand tiles (128 rows x 64 bf16) swizzled, via cp.async
    {
        const __nv_bfloat16* s0 = g_thhi + (size_t)(b * TN + q0) * MIDC;
        const __nv_bfloat16* s1 = g_phhi + (size_t)(b * TN + k0) * MIDC;
        const __nv_bfloat16* s2 = g_phlo + (size_t)(b * TN + k0) * MIDC;
        const __nv_bfloat16* srcs[3] = { s0, s1, s2 };
#pragma unroll
        for (int it = 0; it < 12; it++) {
            int idx = tid + it * 256;            // 0..3071 16B units
            int mat = idx >> 10, row = (idx >> 3) & 127, u = idx & 7;
            CPA16(sb + mat * 16384 + SWZ128(row * 128 + u * 16),
                  (const void*)(srcs[mat] + (size_t)row * MIDC + u * 8));
        }
        CPA_COMMIT();
        asm volatile("cp.async.wait_group 0;" ::: "memory");
    }
    __syncthreads();

    float acc[2][8][4];
#pragma unroll
    for (int i = 0; i < 2; i++)
#pragma unroll
        for (int j = 0; j < 8; j++)
#pragma unroll
            for (int r = 0; r < 4; r++) acc[i][j][r] = 0.f;

    const int arow = wq * 32 + (lane & 15);
    const int acolx = (lane >> 4) << 4;
    const int brow = wk * 64 + (lane & 7) + ((lane >> 4) << 3);
    const int bcolx = ((lane >> 3) & 1) << 4;

#pragma unroll
    for (int ks = 0; ks < 4; ks++) {
        int kb = ks * 32;
        u32 aH0[4], aH1[4];
        ldsm4(aH0, sb + SWZ128(arow * 128 + kb + acolx));
        ldsm4(aH1, sb + SWZ128((arow + 16) * 128 + kb + acolx));
#pragma unroll
        for (int jp = 0; jp < 4; jp++) {
            u32 bH[4], bL[4];
            ldsm4(bH, sb + 16384 + SWZ128((brow + jp * 16) * 128 + kb + bcolx));
            ldsm4(bL, sb + 32768 + SWZ128((brow + jp * 16) * 128 + kb + bcolx));
            // hi * hi
            mma16816(acc[0][2 * jp],     aH0, bH[0], bH[1]);
            mma16816(acc[0][2 * jp + 1], aH0, bH[2], bH[3]);
            mma16816(acc[1][2 * jp],     aH1, bH[0], bH[1]);
            mma16816(acc[1][2 * jp + 1], aH1, bH[2], bH[3]);
            // hi * lo
            mma16816(acc[0][2 * jp],     aH0, bL[0], bL[1]);
            mma16816(acc[0][2 * jp + 1], aH0, bL[2], bL[3]);
            mma16816(acc[1][2 * jp],     aH1, bL[0], bL[1]);
            mma16816(acc[1][2 * jp + 1], aH1, bL[2], bL[3]);
        }
    }
    __syncthreads();                             // operands dead

    // exp in registers (fp32), stage E hi, per-column fp32 partial sums
    float* red = (float*)(smem + 128 * EST);     // 34816: [4 wq][128 k]
#pragma unroll
    for (int i = 0; i < 2; i++)
#pragma unroll
        for (int j = 0; j < 8; j++)
#pragma unroll
            for (int r = 0; r < 4; r++) acc[i][j][r] = fexp(acc[i][j][r]);

#pragma unroll
    for (int i = 0; i < 2; i++) {
        int qr = wq * 32 + i * 16 + (lane >> 2);
#pragma unroll
        for (int j = 0; j < 8; j++) {
            int kc = wk * 64 + j * 8 + 2 * (lane & 3);
            *(u32*)(smem + qr * EST + kc * 2)       = pk_hi2(acc[i][j][0], acc[i][j][1]);
            *(u32*)(smem + (qr + 8) * EST + kc * 2) = pk_hi2(acc[i][j][2], acc[i][j][3]);
        }
    }
#pragma unroll
    for (int j = 0; j < 8; j++) {
        float c0 = (acc[0][j][0] + acc[0][j][2]) + (acc[1][j][0] + acc[1][j][2]);
        float c1 = (acc[0][j][1] + acc[0][j][3]) + (acc[1][j][1] + acc[1][j][3]);
#pragma unroll
        for (int off = 4; off < 32; off <<= 1) {
            c0 += __shfl_xor_sync(0xFFFFFFFFu, c0, off);
            c1 += __shfl_xor_sync(0xFFFFFFFFu, c1, off);
        }
        if (lane < 4) {
            int kc = wk * 64 + j * 8 + 2 * lane;
            red[wq * 128 + kc]     = c0;
            red[wq * 128 + kc + 1] = c1;
        }
    }
    __syncthreads();

    if (tid < 128) {
        float z = (red[tid] + red[128 + tid]) + (red[256 + tid] + red[384 + tid]);
        g_Zp[(qt * BATCH + b) * TN + k0 + tid] = z;
    }

    // coalesced copy-out of E hi: 2 rows per warp per pass, uint4 (16-aligned)
    for (int rp = wid * 2; rp < 128; rp += 16) {
        int row = rp + (lane >> 4);
        int u = lane & 15;
        uint4 v = *(const uint4*)(smem + row * EST + u * 16);
        *(uint4*)&g_Ehi[(size_t)(b * TN + q0 + row) * TN + k0 + u * 8] = v;
    }
}

// ---------------------------------------------------------------------------
// 3) scalegT (invZ fused): gsT [m][k] = bf16(g[k][m]/Z[k])
// ---------------------------------------------------------------------------
__global__ void __launch_bounds__(256)
scalegT_kernel()
{
    __shared__ float s[64][65];
    __shared__ float siz[64];
    const int k0 = blockIdx.x * 64, b = blockIdx.y;
    const int tid = threadIdx.x;
    if (tid < 64) {
        int idx = b * TN + k0 + tid;
        float z = 0.f;
#pragma unroll
        for (int t = 0; t < 16; t++) z += g_Zp[t * 16384 + idx];
        siz[tid] = 1.0f / z;
    }
    __syncthreads();
#pragma unroll
    for (int t = 0; t < 4; t++) {
        int f4 = tid + t * 256;
        int row = f4 >> 4, c4 = (f4 & 15) << 2;
        float iz = siz[row];
        float4 v = *(const float4*)&g_g[(size_t)(b * TN + k0 + row) * MIDC + c4];
        s[row][c4 + 0] = v.x * iz;  s[row][c4 + 1] = v.y * iz;
        s[row][c4 + 2] = v.z * iz;  s[row][c4 + 3] = v.w * iz;
    }
    __syncthreads();
    int m = tid >> 2, kk0 = (tid & 3) << 4;
    u32 hw[8];
#pragma unroll
    for (int j = 0; j < 8; j++)
        hw[j] = pk_hi2(s[kk0 + 2 * j][m], s[kk0 + 2 * j + 1][m]);
    size_t doff = (size_t)(b * MIDC + m) * TN + k0 + kk0;
    *(uint4*)&g_gsThi[doff]     = make_uint4(hw[0], hw[1], hw[2], hw[3]);
    *(uint4*)&g_gsThi[doff + 8] = make_uint4(hw[4], hw[5], hw[6], hw[7]);
}

// ---------------------------------------------------------------------------
// 4) attn_y: y[q][m] = sum_k Ehi[q][k] * gsT[k][m].
//    k-chunk 128 (2 swizzled 64-col subtiles per operand), 3-stage cp.async
//    pipeline (32KB/stage, 96KB dynamic), ONE barrier per chunk, 16 chunks.
// ---------------------------------------------------------------------------
#define AT_SMEM 98304

__global__ void __launch_bounds__(256)
attn_y_kernel()
{
    extern __shared__ char smem[];
    const u32 sb = smem_u32(smem);
    const int qt = blockIdx.x, b = blockIdx.y;
    const int q0 = qt * 64;
    const int tid = threadIdx.x, wid = tid >> 5, lane = tid & 31;
    const int wq = wid >> 1, wm = wid & 1;

    float acc[4][4];
#pragma unroll
    for (int j = 0; j < 4; j++)
#pragma unroll
        for (int r = 0; r < 4; r++) acc[j][r] = 0.f;

    const int arow = wq * 16 + (lane & 15);
    const int acolx = (lane >> 4) << 4;
    const int brow = wm * 32 + (lane & 7) + ((lane >> 4) << 3);
    const int bcolx = ((lane >> 3) & 1) << 4;

    // stage layout (32KB): E0 @0, E1 @8192, gs0 @16384, gs1 @24576
    auto load_stage = [&](int stage, int kc) {
        u32 base = sb + stage * 32768;
#pragma unroll
        for (int it = 0; it < 4; it++) {         // E: 1024 16B units
            int idx = tid + it * 256;
            int half = idx >> 9, row = (idx >> 3) & 63, u = idx & 7;
            CPA16(base + half * 8192 + SWZ128(row * 128 + u * 16),
                  (const void*)&g_Ehi[(size_t)(b * TN + q0 + row) * TN
                                      + kc + half * 64 + u * 8]);
        }
#pragma unroll
        for (int it = 0; it < 4; it++) {         // gs: 1024 16B units
            int idx = tid + it * 256;
            int half = idx >> 9, row = (idx >> 3) & 63, u = idx & 7;
            CPA16(base + 16384 + half * 8192 + SWZ128(row * 128 + u * 16),
                  (const void*)&g_gsThi[(size_t)(b * MIDC + row) * TN
                                        + kc + half * 64 + u * 8]);
        }
        CPA_COMMIT();
    };

    load_stage(0, 0);
    load_stage(1, 128);
    for (int ch = 0; ch < 16; ch++) {
        if (ch == 15) asm volatile("cp.async.wait_group 0;" ::: "memory");
        else          asm volatile("cp.async.wait_group 1;" ::: "memory");
        __syncthreads();                         // buffer ch visible; MMA(ch-1) done
        if (ch + 2 < 16) load_stage((ch + 2) % 3, (ch + 2) * 128);
        u32 base = sb + (ch % 3) * 32768;
#pragma unroll
        for (int half = 0; half < 2; half++) {
            u32 bA = base + half * 8192;
            u32 bB = base + 16384 + half * 8192;
#pragma unroll
            for (int ks = 0; ks < 4; ks++) {
                int kb = ks * 32;
                u32 a0[4];
                ldsm4(a0, bA + SWZ128(arow * 128 + kb + acolx));
#pragma unroll
                for (int jp = 0; jp < 2; jp++) {
                    u32 bb[4];
                    ldsm4(bb, bB + SWZ128((brow + jp * 16) * 128 + kb + bcolx));
                    mma16816(acc[2 * jp],     a0, bb[0], bb[1]);
                    mma16816(acc[2 * jp + 1], a0, bb[2], bb[3]);
                }
            }
        }
    }
    __syncthreads();                             // all MMA done before ys overlay

    // epilogue: stage D[64 q][64 m] fp32 (stride 65), write y^T[m][q]
    float* ys = (float*)smem;
    {
        int qr = wq * 16 + (lane >> 2);
#pragma unroll
        for (int j = 0; j < 4; j++) {
            int mc = wm * 32 + j * 8 + 2 * (lane & 3);
            ys[qr * 65 + mc]           = acc[j][0];
            ys[qr * 65 + mc + 1]       = acc[j][1];
            ys[(qr + 8) * 65 + mc]     = acc[j][2];
            ys[(qr + 8) * 65 + mc + 1] = acc[j][3];
        }
    }
    __syncthreads();
    for (int m = wid; m < 64; m += 8) {
        float2 f = make_float2(ys[(lane * 2 + 0) * 65 + m],
                               ys[(lane * 2 + 1) * 65 + m]);
        *(float2*)&g_yT[(size_t)(b * MIDC + m) * TN + q0 + lane * 2] = f;
    }
}

// ---------------------------------------------------------------------------
// 5) refine (FFMA2): refined[q][o] = relu(sum_m yT[m][q]*rw[o][m] + rb[o])
// ---------------------------------------------------------------------------
__global__ void __launch_bounds__(256)
refine_kernel(const float* __restrict__ RW, const float* __restrict__ RB)
{
    __shared__ float As[32 * 128];
    __shared__ float Bs[32 * 128];
    const int b = blockIdx.z;
    const int q0 = blockIdx.x * 128;
    const float* Yb = g_yT + (size_t)b * MIDC * TN;
    const int tid = threadIdx.x;
    const int tx = tid & 15, ty = tid >> 4;

    u64 acc[8][4];
#pragma unroll
    for (int i = 0; i < 8; i++)
#pragma unroll
        for (int j = 0; j < 4; j++) acc[i][j] = 0ULL;

    for (int mt = 0; mt < MIDC; mt += 32) {
#pragma unroll
        for (int t = 0; t < 4; t++) {
            int f4 = tid + t * 256;
            int mm = f4 >> 5, c4 = (f4 & 31) << 2;
            *(float4*)&As[mm * 128 + c4] =
                *(const float4*)&Yb[(size_t)(mt + mm) * TN + q0 + c4];
        }
#pragma unroll
        for (int t = 0; t < 4; t++) {
            int f4 = tid + t * 256;
            int o = f4 >> 3, c4 = (f4 & 7) << 2;
            float4 w4 = *(const float4*)&RW[o * MIDC + mt + c4];
            Bs[(c4 + 0) * 128 + o] = w4.x;  Bs[(c4 + 1) * 128 + o] = w4.y;
            Bs[(c4 + 2) * 128 + o] = w4.z;  Bs[(c4 + 3) * 128 + o] = w4.w;
        }
        __syncthreads();
#pragma unroll 8
        for (int mm = 0; mm < 32; mm++) {
            float4 a0 = *(float4*)&As[mm * 128 + ty * 8];
            float4 a1 = *(float4*)&As[mm * 128 + ty * 8 + 4];
            ulonglong2 b01 = *(ulonglong2*)&Bs[mm * 128 + tx * 8];
            ulonglong2 b23 = *(ulonglong2*)&Bs[mm * 128 + tx * 8 + 4];
            u64 aa[8] = { splat2(a0.x), splat2(a0.y), splat2(a0.z), splat2(a0.w),
                          splat2(a1.x), splat2(a1.y), splat2(a1.z), splat2(a1.w) };
            u64 bb[4] = { b01.x, b01.y, b23.x, b23.y };
#pragma unroll
            for (int i = 0; i < 8; i++)
#pragma unroll
                for (int j = 0; j < 4; j++)
                    acc[i][j] = fma2_(aa[i], bb[j], acc[i][j]);
        }
        __syncthreads();
    }

    float* Rb = g_ref + (size_t)b * TN * OUTC;
    float rbv[8];
#pragma unroll
    for (int j = 0; j < 8; j++) rbv[j] = RB[tx * 8 + j];
#pragma unroll
    for (int i = 0; i < 8; i++) {
        float v[8];
#pragma unroll
        for (int j2 = 0; j2 < 4; j2++) upk2(acc[i][j2], v[2 * j2], v[2 * j2 + 1]);
#pragma unroll
        for (int j = 0; j < 8; j++) v[j] = fmaxf(v[j] + rbv[j], 0.f);
        size_t row = (size_t)(q0 + ty * 8 + i) * OUTC + tx * 8;
        *(float4*)&Rb[row]     = make_float4(v[0], v[1], v[2], v[3]);
        *(float4*)&Rb[row + 4] = make_float4(v[4], v[5], v[6], v[7]);
    }
}

// ---------------------------------------------------------------------------
// 6) out[b,c,t,n] = refined[b][q][o] + pc, q=(n&15)*128+c, o=t*32+(n>>4)
// ---------------------------------------------------------------------------
__global__ void __launch_bounds__(256)
scatter_kernel(const float* __restrict__ pc, float* __restrict__ out)
{
    int i4 = blockIdx.x * 256 + threadIdx.x;     // 524288 float4 tasks
    int idx = i4 << 2;
    int b = idx >> 18;
    int r = idx & 262143;
    int c = r >> 11;
    int t = (r >> 9) & 3;
    int n = r & 511;
    int o = (t << 5) + (n >> 4);
    int qb = ((n & 15) << 7) + c;
    const float* Rb = g_ref + ((size_t)b << 18) + o;
    float4 p = *(const float4*)&pc[idx];
    float4 v;
    v.x = Rb[(qb       ) << 7] + p.x;
    v.y = Rb[(qb +  128) << 7] + p.y;
    v.z = Rb[(qb +  256) << 7] + p.z;
    v.w = Rb[(qb +  384) << 7] + p.w;
    *(float4*)&out[idx] = v;
}

// ---------------------------------------------------------------------------
// Host launcher
// ---------------------------------------------------------------------------
extern "C" void kernel_launch(void* const* d_in, const int* in_sizes, int n_in,
                              void* d_out, int out_size)
{
    const float* pc = (const float*)d_in[0];
    const float* tw = (const float*)d_in[1];
    const float* tb = (const float*)d_in[2];
    const float* pw = (const float*)d_in[3];
    const float* pb = (const float*)d_in[4];
    const float* gw = (const float*)d_in[5];
    const float* gb = (const float*)d_in[6];
    const float* rw = (const float*)d_in[7];
    const float* rb = (const float*)d_in[8];
    float* out = (float*)d_out;

    cudaFuncSetAttribute(attn_y_kernel,
                         cudaFuncAttributeMaxDynamicSharedMemorySize, AT_SMEM);

    proj_kernel   <<<dim3(16, 3, BATCH), 256>>>(pc, tw, tb, pw, pb, gw, gb);
    scores_kernel <<<dim3(16, 16, BATCH), 256, SC_SMEM>>>();
    scalegT_kernel<<<dim3(32, BATCH), 256>>>();
    attn_y_kernel <<<dim3(32, BATCH), 256, AT_SMEM>>>();
    refine_kernel <<<dim3(16, 1, BATCH), 256>>>(rw, rb);
    scatter_kernel<<<2048, 256>>>(pc, out);
}

// round 15
// speedup vs baseline: 2.0606x; 1.0359x over previous
#include <cuda_runtime.h>
#include <cuda_bf16.h>

#define BATCH 8
#define CH    128
#define MIDC  64
#define OUTC  128
#define TN    2048

typedef unsigned long long u64;
typedef unsigned int u32;

// ---------------------------------------------------------------------------
// Scratch (device globals; allocation-free per harness rules)
// ---------------------------------------------------------------------------
__device__ __nv_bfloat16 g_thhi[BATCH * TN * MIDC];     // theta hi [b][q][m]
__device__ __nv_bfloat16 g_phhi[BATCH * TN * MIDC];     // phi hi [b][k][m]
__device__ __nv_bfloat16 g_phlo[BATCH * TN * MIDC];     // phi lo
__device__ float         g_g   [BATCH * TN * MIDC];     // g fp32 [b][k][m]
__device__ __nv_bfloat16 g_Ehi [(size_t)BATCH * TN * TN]; // exp(s) bf16 [b][q][k]
__device__ float g_Zp  [16 * BATCH * TN];
__device__ __nv_bfloat16 g_gsThi[BATCH * MIDC * TN];    // (g*invZ)^T bf16 [b][m][k]
__device__ __nv_bfloat16 g_yhi [BATCH * TN * MIDC];     // y hi bf16 [b][q][m]
__device__ __nv_bfloat16 g_ylo [BATCH * TN * MIDC];     // y lo bf16 [b][q][m]
__device__ float g_ref[BATCH * TN * OUTC];              // [b][q][o]

// ---------------------------------------------------------------------------
// PTX helpers (base ISA only)
// ---------------------------------------------------------------------------
__device__ __forceinline__ u32 smem_u32(const void* p) {
    u32 a; asm("{ .reg .u64 t; cvta.to.shared.u64 t, %1; cvt.u32.u64 %0, t; }"
               : "=r"(a) : "l"(p)); return a;
}
#define SWZ128(x) ((x) ^ (((x) >> 3) & 0x70))

__device__ __forceinline__ void ldsm4(u32* r, u32 addr) {
    asm volatile("ldmatrix.sync.aligned.m8n8.x4.shared.b16 {%0,%1,%2,%3}, [%4];"
        : "=r"(r[0]), "=r"(r[1]), "=r"(r[2]), "=r"(r[3]) : "r"(addr));
}
__device__ __forceinline__ void mma16816(float* d, const u32* a, u32 b0, u32 b1) {
    asm volatile("mma.sync.aligned.m16n8k16.row.col.f32.bf16.bf16.f32 "
        "{%0,%1,%2,%3}, {%4,%5,%6,%7}, {%8,%9}, {%0,%1,%2,%3};"
        : "+f"(d[0]), "+f"(d[1]), "+f"(d[2]), "+f"(d[3])
        : "r"(a[0]), "r"(a[1]), "r"(a[2]), "r"(a[3]), "r"(b0), "r"(b1));
}
#define CPA16(dst, src) \
    asm volatile("cp.async.cg.shared.global [%0], [%1], 16;" \
                 :: "r"(dst), "l"(src) : "memory")
#define CPA_COMMIT() asm volatile("cp.async.commit_group;" ::: "memory")

// fp32x2 + fast exp helpers
__device__ __forceinline__ u64 splat2(float x) {
    u64 r; asm("mov.b64 %0,{%1,%1};" : "=l"(r) : "f"(x)); return r;
}
__device__ __forceinline__ u64 fma2_(u64 a, u64 b, u64 c) {
    u64 d; asm("fma.rn.f32x2 %0,%1,%2,%3;" : "=l"(d) : "l"(a), "l"(b), "l"(c)); return d;
}
__device__ __forceinline__ void upk2(u64 p, float& a, float& b) {
    asm("mov.b64 {%0,%1},%2;" : "=f"(a), "=f"(b) : "l"(p));
}
__device__ __forceinline__ float fexp(float x) {
    const float L2E = 1.4426950408889634f;
    float z = fmaf(x, L2E, 12582912.0f);
    float n = z - 12582912.0f;
    float f = fmaf(x, L2E, -n);
    float p =          1.3333558146e-3f;
    p = fmaf(p, f,     9.6181291076e-3f);
    p = fmaf(p, f,     5.5504108665e-2f);
    p = fmaf(p, f,     2.4022650696e-1f);
    p = fmaf(p, f,     6.9314718056e-1f);
    p = fmaf(p, f,     1.0f);
    int ni = __float_as_int(z) - 0x4B400000;
    return p * __int_as_float((ni + 127) << 23);
}
__device__ __forceinline__ u32 pkbf(__nv_bfloat16 a, __nv_bfloat16 b) {
    return (u32)__bfloat16_as_ushort(a) | ((u32)__bfloat16_as_ushort(b) << 16);
}
__device__ __forceinline__ u32 pk_hi2(float x, float y) {
    return pkbf(__float2bfloat16(x), __float2bfloat16(y));
}
__device__ __forceinline__ u32 pk_lo2(float x, float y) {
    __nv_bfloat16 hx = __float2bfloat16(x), hy = __float2bfloat16(y);
    return pkbf(__float2bfloat16(x - __bfloat162float(hx)),
                __float2bfloat16(y - __bfloat162float(hy)));
}

// ---------------------------------------------------------------------------
// 1) Projections: relu(W[64x128]*pc[128x2048]+b).
//    theta -> bf16 hi [tn][64]; phi -> bf16 hi/lo; g -> fp32.
// ---------------------------------------------------------------------------
__global__ void __launch_bounds__(256)
proj_kernel(const float* __restrict__ pc,
            const float* __restrict__ tw, const float* __restrict__ tb,
            const float* __restrict__ pw, const float* __restrict__ pb,
            const float* __restrict__ gw, const float* __restrict__ gb)
{
    __shared__ float As[32 * 64];
    __shared__ float Bs[32 * 128];
    const int b = blockIdx.z, pj = blockIdx.y;
    const int n0 = blockIdx.x * 128;
    const float *W, *bi;
    if (pj == 0)      { W = tw; bi = tb; }
    else if (pj == 1) { W = pw; bi = pb; }
    else              { W = gw; bi = gb; }
    const float* pcb = pc + (size_t)b * CH * TN;
    const int tid = threadIdx.x;
    const int tx = tid & 15, ty = tid >> 4;

    u64 acc[4][4];
#pragma unroll
    for (int i = 0; i < 4; i++)
#pragma unroll
        for (int j = 0; j < 4; j++) acc[i][j] = 0ULL;

    for (int ct = 0; ct < 128; ct += 32) {
#pragma unroll
        for (int t = 0; t < 2; t++) {
            int f4 = tid + t * 256;
            int m = f4 >> 3, c4 = (f4 & 7) << 2;
            float4 w4 = *(const float4*)&W[m * 128 + ct + c4];
            As[(c4 + 0) * 64 + m] = w4.x;  As[(c4 + 1) * 64 + m] = w4.y;
            As[(c4 + 2) * 64 + m] = w4.z;  As[(c4 + 3) * 64 + m] = w4.w;
        }
#pragma unroll
        for (int t = 0; t < 4; t++) {
            int f4 = tid + t * 256;
            int cc = f4 >> 5, c4 = (f4 & 31) << 2;
            *(float4*)&Bs[cc * 128 + c4] =
                *(const float4*)&pcb[(size_t)(ct + cc) * TN + n0 + c4];
        }
        __syncthreads();
#pragma unroll 8
        for (int cc = 0; cc < 32; cc++) {
            float4 av = *(float4*)&As[cc * 64 + ty * 4];
            ulonglong2 b01 = *(ulonglong2*)&Bs[cc * 128 + tx * 8];
            ulonglong2 b23 = *(ulonglong2*)&Bs[cc * 128 + tx * 8 + 4];
            u64 aa[4] = { splat2(av.x), splat2(av.y), splat2(av.z), splat2(av.w) };
            u64 bb[4] = { b01.x, b01.y, b23.x, b23.y };
#pragma unroll
            for (int i = 0; i < 4; i++)
#pragma unroll
                for (int j = 0; j < 4; j++)
                    acc[i][j] = fma2_(aa[i], bb[j], acc[i][j]);
        }
        __syncthreads();
    }

    float v[4][8];
#pragma unroll
    for (int i = 0; i < 4; i++) {
#pragma unroll
        for (int j2 = 0; j2 < 4; j2++) upk2(acc[i][j2], v[i][2 * j2], v[i][2 * j2 + 1]);
        float bv = bi[ty * 4 + i];
#pragma unroll
        for (int j = 0; j < 8; j++) v[i][j] = fmaxf(v[i][j] + bv, 0.f);
    }
    if (pj == 0) {                               // theta: hi only
        __nv_bfloat16* oh = g_thhi + (size_t)b * TN * MIDC;
#pragma unroll
        for (int j = 0; j < 8; j++) {
            int tn = n0 + tx * 8 + j;
            *(uint2*)&oh[(size_t)tn * MIDC + ty * 4] =
                make_uint2(pk_hi2(v[0][j], v[1][j]), pk_hi2(v[2][j], v[3][j]));
        }
    } else if (pj == 1) {                        // phi: hi + lo
        __nv_bfloat16* oh = g_phhi + (size_t)b * TN * MIDC;
        __nv_bfloat16* ol = g_phlo + (size_t)b * TN * MIDC;
#pragma unroll
        for (int j = 0; j < 8; j++) {
            int tn = n0 + tx * 8 + j;
            *(uint2*)&oh[(size_t)tn * MIDC + ty * 4] =
                make_uint2(pk_hi2(v[0][j], v[1][j]), pk_hi2(v[2][j], v[3][j]));
            *(uint2*)&ol[(size_t)tn * MIDC + ty * 4] =
                make_uint2(pk_lo2(v[0][j], v[1][j]), pk_lo2(v[2][j], v[3][j]));
        }
    } else {
        float* ob = g_g + (size_t)b * TN * MIDC;
#pragma unroll
        for (int j = 0; j < 8; j++)
            *(float4*)&ob[(size_t)(n0 + tx * 8 + j) * MIDC + ty * 4] =
                make_float4(v[0][j], v[1][j], v[2][j], v[3][j]);
    }
}

// ---------------------------------------------------------------------------
// 2) scores: warp-MMA bf16 2-pass (th_hi x ph_hi + th_hi x ph_lo), fused
//    exp + register colsum, E hi store. cp.async operand loads.
// ---------------------------------------------------------------------------
#define SC_SMEM 49152
#define EST 272                                   // staging row stride bytes

__global__ void __launch_bounds__(256)
scores_kernel()
{
    extern __shared__ char smem[];
    const u32 sb = smem_u32(smem);
    const int b = blockIdx.z, qt = blockIdx.y, kt = blockIdx.x;
    const int q0 = qt * 128, k0 = kt * 128;
    const int tid = threadIdx.x, wid = tid >> 5, lane = tid & 31;
    const int wq = wid >> 1, wk = wid & 1;

    // load 3 operand tiles (128 rows x 64 bf16) swizzled, via cp.async
    {
        const __nv_bfloat16* s0 = g_thhi + (size_t)(b * TN + q0) * MIDC;
        const __nv_bfloat16* s1 = g_phhi + (size_t)(b * TN + k0) * MIDC;
        const __nv_bfloat16* s2 = g_phlo + (size_t)(b * TN + k0) * MIDC;
        const __nv_bfloat16* srcs[3] = { s0, s1, s2 };
#pragma unroll
        for (int it = 0; it < 12; it++) {
            int idx = tid + it * 256;            // 0..3071 16B units
            int mat = idx >> 10, row = (idx >> 3) & 127, u = idx & 7;
            CPA16(sb + mat * 16384 + SWZ128(row * 128 + u * 16),
                  (const void*)(srcs[mat] + (size_t)row * MIDC + u * 8));
        }
        CPA_COMMIT();
        asm volatile("cp.async.wait_group 0;" ::: "memory");
    }
    __syncthreads();

    float acc[2][8][4];
#pragma unroll
    for (int i = 0; i < 2; i++)
#pragma unroll
        for (int j = 0; j < 8; j++)
#pragma unroll
            for (int r = 0; r < 4; r++) acc[i][j][r] = 0.f;

    const int arow = wq * 32 + (lane & 15);
    const int acolx = (lane >> 4) << 4;
    const int brow = wk * 64 + (lane & 7) + ((lane >> 4) << 3);
    const int bcolx = ((lane >> 3) & 1) << 4;

#pragma unroll
    for (int ks = 0; ks < 4; ks++) {
        int kb = ks * 32;
        u32 aH0[4], aH1[4];
        ldsm4(aH0, sb + SWZ128(arow * 128 + kb + acolx));
        ldsm4(aH1, sb + SWZ128((arow + 16) * 128 + kb + acolx));
#pragma unroll
        for (int jp = 0; jp < 4; jp++) {
            u32 bH[4], bL[4];
            ldsm4(bH, sb + 16384 + SWZ128((brow + jp * 16) * 128 + kb + bcolx));
            ldsm4(bL, sb + 32768 + SWZ128((brow + jp * 16) * 128 + kb + bcolx));
            // hi * hi
            mma16816(acc[0][2 * jp],     aH0, bH[0], bH[1]);
            mma16816(acc[0][2 * jp + 1], aH0, bH[2], bH[3]);
            mma16816(acc[1][2 * jp],     aH1, bH[0], bH[1]);
            mma16816(acc[1][2 * jp + 1], aH1, bH[2], bH[3]);
            // hi * lo
            mma16816(acc[0][2 * jp],     aH0, bL[0], bL[1]);
            mma16816(acc[0][2 * jp + 1], aH0, bL[2], bL[3]);
            mma16816(acc[1][2 * jp],     aH1, bL[0], bL[1]);
            mma16816(acc[1][2 * jp + 1], aH1, bL[2], bL[3]);
        }
    }
    __syncthreads();                             // operands dead

    // exp in registers (fp32), stage E hi, per-column fp32 partial sums
    float* red = (float*)(smem + 128 * EST);     // 34816: [4 wq][128 k]
#pragma unroll
    for (int i = 0; i < 2; i++)
#pragma unroll
        for (int j = 0; j < 8; j++)
#pragma unroll
            for (int r = 0; r < 4; r++) acc[i][j][r] = fexp(acc[i][j][r]);

#pragma unroll
    for (int i = 0; i < 2; i++) {
        int qr = wq * 32 + i * 16 + (lane >> 2);
#pragma unroll
        for (int j = 0; j < 8; j++) {
            int kc = wk * 64 + j * 8 + 2 * (lane & 3);
            *(u32*)(smem + qr * EST + kc * 2)       = pk_hi2(acc[i][j][0], acc[i][j][1]);
            *(u32*)(smem + (qr + 8) * EST + kc * 2) = pk_hi2(acc[i][j][2], acc[i][j][3]);
        }
    }
#pragma unroll
    for (int j = 0; j < 8; j++) {
        float c0 = (acc[0][j][0] + acc[0][j][2]) + (acc[1][j][0] + acc[1][j][2]);
        float c1 = (acc[0][j][1] + acc[0][j][3]) + (acc[1][j][1] + acc[1][j][3]);
#pragma unroll
        for (int off = 4; off < 32; off <<= 1) {
            c0 += __shfl_xor_sync(0xFFFFFFFFu, c0, off);
            c1 += __shfl_xor_sync(0xFFFFFFFFu, c1, off);
        }
        if (lane < 4) {
            int kc = wk * 64 + j * 8 + 2 * lane;
            red[wq * 128 + kc]     = c0;
            red[wq * 128 + kc + 1] = c1;
        }
    }
    __syncthreads();

    if (tid < 128) {
        float z = (red[tid] + red[128 + tid]) + (red[256 + tid] + red[384 + tid]);
        g_Zp[(qt * BATCH + b) * TN + k0 + tid] = z;
    }

    // coalesced copy-out of E hi: 2 rows per warp per pass, uint4 (16-aligned)
    for (int rp = wid * 2; rp < 128; rp += 16) {
        int row = rp + (lane >> 4);
        int u = lane & 15;
        uint4 v = *(const uint4*)(smem + row * EST + u * 16);
        *(uint4*)&g_Ehi[(size_t)(b * TN + q0 + row) * TN + k0 + u * 8] = v;
    }
}

// ---------------------------------------------------------------------------
// 3) scalegT (invZ fused): gsT [m][k] = bf16(g[k][m]/Z[k])
// ---------------------------------------------------------------------------
__global__ void __launch_bounds__(256)
scalegT_kernel()
{
    __shared__ float s[64][65];
    __shared__ float siz[64];
    const int k0 = blockIdx.x * 64, b = blockIdx.y;
    const int tid = threadIdx.x;
    if (tid < 64) {
        int idx = b * TN + k0 + tid;
        float z = 0.f;
#pragma unroll
        for (int t = 0; t < 16; t++) z += g_Zp[t * 16384 + idx];
        siz[tid] = 1.0f / z;
    }
    __syncthreads();
#pragma unroll
    for (int t = 0; t < 4; t++) {
        int f4 = tid + t * 256;
        int row = f4 >> 4, c4 = (f4 & 15) << 2;
        float iz = siz[row];
        float4 v = *(const float4*)&g_g[(size_t)(b * TN + k0 + row) * MIDC + c4];
        s[row][c4 + 0] = v.x * iz;  s[row][c4 + 1] = v.y * iz;
        s[row][c4 + 2] = v.z * iz;  s[row][c4 + 3] = v.w * iz;
    }
    __syncthreads();
    int m = tid >> 2, kk0 = (tid & 3) << 4;
    u32 hw[8];
#pragma unroll
    for (int j = 0; j < 8; j++)
        hw[j] = pk_hi2(s[kk0 + 2 * j][m], s[kk0 + 2 * j + 1][m]);
    size_t doff = (size_t)(b * MIDC + m) * TN + k0 + kk0;
    *(uint4*)&g_gsThi[doff]     = make_uint4(hw[0], hw[1], hw[2], hw[3]);
    *(uint4*)&g_gsThi[doff + 8] = make_uint4(hw[4], hw[5], hw[6], hw[7]);
}

// ---------------------------------------------------------------------------
// 4) attn_y: y[q][m] = sum_k Ehi[q][k] * gsT[k][m].
//    k-chunk 128, 3-stage cp.async pipeline (32KB/stage), 1 barrier/chunk.
//    Epilogue: pack fragments directly to y hi/lo bf16 [q][m] (no staging).
// ---------------------------------------------------------------------------
#define AT_SMEM 98304

__global__ void __launch_bounds__(256)
attn_y_kernel()
{
    extern __shared__ char smem[];
    const u32 sb = smem_u32(smem);
    const int qt = blockIdx.x, b = blockIdx.y;
    const int q0 = qt * 64;
    const int tid = threadIdx.x, wid = tid >> 5, lane = tid & 31;
    const int wq = wid >> 1, wm = wid & 1;

    float acc[4][4];
#pragma unroll
    for (int j = 0; j < 4; j++)
#pragma unroll
        for (int r = 0; r < 4; r++) acc[j][r] = 0.f;

    const int arow = wq * 16 + (lane & 15);
    const int acolx = (lane >> 4) << 4;
    const int brow = wm * 32 + (lane & 7) + ((lane >> 4) << 3);
    const int bcolx = ((lane >> 3) & 1) << 4;

    // stage layout (32KB): E0 @0, E1 @8192, gs0 @16384, gs1 @24576
    auto load_stage = [&](int stage, int kc) {
        u32 base = sb + stage * 32768;
#pragma unroll
        for (int it = 0; it < 4; it++) {         // E: 1024 16B units
            int idx = tid + it * 256;
            int half = idx >> 9, row = (idx >> 3) & 63, u = idx & 7;
            CPA16(base + half * 8192 + SWZ128(row * 128 + u * 16),
                  (const void*)&g_Ehi[(size_t)(b * TN + q0 + row) * TN
                                      + kc + half * 64 + u * 8]);
        }
#pragma unroll
        for (int it = 0; it < 4; it++) {         // gs: 1024 16B units
            int idx = tid + it * 256;
            int half = idx >> 9, row = (idx >> 3) & 63, u = idx & 7;
            CPA16(base + 16384 + half * 8192 + SWZ128(row * 128 + u * 16),
                  (const void*)&g_gsThi[(size_t)(b * MIDC + row) * TN
                                        + kc + half * 64 + u * 8]);
        }
        CPA_COMMIT();
    };

    load_stage(0, 0);
    load_stage(1, 128);
    for (int ch = 0; ch < 16; ch++) {
        if (ch == 15) asm volatile("cp.async.wait_group 0;" ::: "memory");
        else          asm volatile("cp.async.wait_group 1;" ::: "memory");
        __syncthreads();                         // buffer ch visible; MMA(ch-1) done
        if (ch + 2 < 16) load_stage((ch + 2) % 3, (ch + 2) * 128);
        u32 base = sb + (ch % 3) * 32768;
#pragma unroll
        for (int half = 0; half < 2; half++) {
            u32 bA = base + half * 8192;
            u32 bB = base + 16384 + half * 8192;
#pragma unroll
            for (int ks = 0; ks < 4; ks++) {
                int kb = ks * 32;
                u32 a0[4];
                ldsm4(a0, bA + SWZ128(arow * 128 + kb + acolx));
#pragma unroll
                for (int jp = 0; jp < 2; jp++) {
                    u32 bb[4];
                    ldsm4(bb, bB + SWZ128((brow + jp * 16) * 128 + kb + bcolx));
                    mma16816(acc[2 * jp],     a0, bb[0], bb[1]);
                    mma16816(acc[2 * jp + 1], a0, bb[2], bb[3]);
                }
            }
        }
    }

    // epilogue: pack fragments to y hi/lo bf16 [b][q][m] (register-only)
    {
        int qr = wq * 16 + (lane >> 2);
#pragma unroll
        for (int j = 0; j < 4; j++) {
            int mc = wm * 32 + j * 8 + 2 * (lane & 3);
            size_t r0 = (size_t)(b * TN + q0 + qr) * MIDC + mc;
            size_t r1 = (size_t)(b * TN + q0 + qr + 8) * MIDC + mc;
            *(u32*)&g_yhi[r0] = pk_hi2(acc[j][0], acc[j][1]);
            *(u32*)&g_ylo[r0] = pk_lo2(acc[j][0], acc[j][1]);
            *(u32*)&g_yhi[r1] = pk_hi2(acc[j][2], acc[j][3]);
            *(u32*)&g_ylo[r1] = pk_lo2(acc[j][2], acc[j][3]);
        }
    }
}

// ---------------------------------------------------------------------------
// 5) refine: 3-pass bf16 HMMA. refined[q][o] = relu(y[q][m]*rw[o][m] + rb[o])
//    q-tile 64 -> grid 256.  smem: YH 0 / YL 8192 / WH 16384 / WL 32768 /
//    bias 49152.  rw converted fp32->hi/lo in prologue.
// ---------------------------------------------------------------------------
#define RF_SMEM 49664

__global__ void __launch_bounds__(256)
refine_kernel(const float* __restrict__ RW, const float* __restrict__ RB)
{
    extern __shared__ char smem[];
    const u32 sb = smem_u32(smem);
    const int b = blockIdx.y;
    const int q0 = blockIdx.x * 64;
    const int tid = threadIdx.x, wid = tid >> 5, lane = tid & 31;
    const int wq = wid >> 2, wo = wid & 3;       // q half (32), o quarter (32)
    float* bias = (float*)(smem + 49152);

    // load Y hi/lo tiles [64 q][64 m] via cp.async (swizzled)
    {
        const __nv_bfloat16* s0 = g_yhi + (size_t)(b * TN + q0) * MIDC;
        const __nv_bfloat16* s1 = g_ylo + (size_t)(b * TN + q0) * MIDC;
#pragma unroll
        for (int it = 0; it < 4; it++) {
            int idx = tid + it * 256;            // 0..1023
            int mat = idx >> 9, row = (idx >> 3) & 63, u = idx & 7;
            CPA16(sb + mat * 8192 + SWZ128(row * 128 + u * 16),
                  (const void*)((mat ? s1 : s0) + (size_t)row * MIDC + u * 8));
        }
        CPA_COMMIT();
    }
    // convert rw fp32 -> bf16 hi/lo [o][m] swizzled (8 float4 per thread)
#pragma unroll
    for (int t = 0; t < 8; t++) {
        int f4 = tid + t * 256;                  // 0..2047
        int o = f4 >> 4, m4 = (f4 & 15) << 2;
        float4 w = *(const float4*)&RW[o * MIDC + m4];
        u32 off = SWZ128(o * 128 + m4 * 2);      // 8B-aligned, swizzle-safe
        *(u64*)(smem + 16384 + off) =
            ((u64)pk_hi2(w.z, w.w) << 32) | pk_hi2(w.x, w.y);
        *(u64*)(smem + 32768 + off) =
            ((u64)pk_lo2(w.z, w.w) << 32) | pk_lo2(w.x, w.y);
    }
    if (tid < 128) bias[tid] = RB[tid];
    asm volatile("cp.async.wait_group 0;" ::: "memory");
    __syncthreads();

    float acc[2][4][4];
#pragma unroll
    for (int i = 0; i < 2; i++)
#pragma unroll
        for (int j = 0; j < 4; j++)
#pragma unroll
            for (int r = 0; r < 4; r++) acc[i][j][r] = 0.f;

    const int arow = wq * 32 + (lane & 15);
    const int acolx = (lane >> 4) << 4;
    const int brow = wo * 32 + (lane & 7) + ((lane >> 4) << 3);
    const int bcolx = ((lane >> 3) & 1) << 4;

#pragma unroll
    for (int ks = 0; ks < 4; ks++) {
        int kb = ks * 32;
        u32 aH0[4], aH1[4], aL0[4], aL1[4];
        ldsm4(aH0, sb        + SWZ128(arow * 128 + kb + acolx));
        ldsm4(aH1, sb        + SWZ128((arow + 16) * 128 + kb + acolx));
        ldsm4(aL0, sb + 8192 + SWZ128(arow * 128 + kb + acolx));
        ldsm4(aL1, sb + 8192 + SWZ128((arow + 16) * 128 + kb + acolx));
#pragma unroll
        for (int jp = 0; jp < 2; jp++) {
            u32 bH[4], bL[4];
            ldsm4(bH, sb + 16384 + SWZ128((brow + jp * 16) * 128 + kb + bcolx));
            ldsm4(bL, sb + 32768 + SWZ128((brow + jp * 16) * 128 + kb + bcolx));
            // hi * hi
            mma16816(acc[0][2 * jp],     aH0, bH[0], bH[1]);
            mma16816(acc[0][2 * jp + 1], aH0, bH[2], bH[3]);
            mma16816(acc[1][2 * jp],     aH1, bH[0], bH[1]);
            mma16816(acc[1][2 * jp + 1], aH1, bH[2], bH[3]);
            // hi * lo
            mma16816(acc[0][2 * jp],     aH0, bL[0], bL[1]);
            mma16816(acc[0][2 * jp + 1], aH0, bL[2], bL[3]);
            mma16816(acc[1][2 * jp],     aH1, bL[0], bL[1]);
            mma16816(acc[1][2 * jp + 1], aH1, bL[2], bL[3]);
            // lo * hi
            mma16816(acc[0][2 * jp],     aL0, bH[0], bH[1]);
            mma16816(acc[0][2 * jp + 1], aL0, bH[2], bH[3]);
            mma16816(acc[1][2 * jp],     aL1, bH[0], bH[1]);
            mma16816(acc[1][2 * jp + 1], aL1, bH[2], bH[3]);
        }
    }

    // epilogue: bias + relu, direct float2 stores to g_ref [q][o]
    float* Rb = g_ref + (size_t)b * TN * OUTC;
#pragma unroll
    for (int i = 0; i < 2; i++) {
        int qr = q0 + wq * 32 + i * 16 + (lane >> 2);
#pragma unroll
        for (int j = 0; j < 4; j++) {
            int oc = wo * 32 + j * 8 + 2 * (lane & 3);
            float b0 = bias[oc], b1 = bias[oc + 1];
            float2 v0 = make_float2(fmaxf(acc[i][j][0] + b0, 0.f),
                                    fmaxf(acc[i][j][1] + b1, 0.f));
            float2 v1 = make_float2(fmaxf(acc[i][j][2] + b0, 0.f),
                                    fmaxf(acc[i][j][3] + b1, 0.f));
            *(float2*)&Rb[(size_t)qr * OUTC + oc]       = v0;
            *(float2*)&Rb[(size_t)(qr + 8) * OUTC + oc] = v1;
        }
    }
}

// ---------------------------------------------------------------------------
// 6) out[b,c,t,n] = refined[b][q][o] + pc, q=(n&15)*128+c, o=t*32+(n>>4)
// ---------------------------------------------------------------------------
__global__ void __launch_bounds__(256)
scatter_kernel(const float* __restrict__ pc, float* __restrict__ out)
{
    int i4 = blockIdx.x * 256 + threadIdx.x;     // 524288 float4 tasks
    int idx = i4 << 2;
    int b = idx >> 18;
    int r = idx & 262143;
    int c = r >> 11;
    int t = (r >> 9) & 3;
    int n = r & 511;
    int o = (t << 5) + (n >> 4);
    int qb = ((n & 15) << 7) + c;
    const float* Rb = g_ref + ((size_t)b << 18) + o;
    float4 p = *(const float4*)&pc[idx];
    float4 v;
    v.x = Rb[(qb       ) << 7] + p.x;
    v.y = Rb[(qb +  128) << 7] + p.y;
    v.z = Rb[(qb +  256) << 7] + p.z;
    v.w = Rb[(qb +  384) << 7] + p.w;
    *(float4*)&out[idx] = v;
}

// ---------------------------------------------------------------------------
// Host launcher
// ---------------------------------------------------------------------------
extern "C" void kernel_launch(void* const* d_in, const int* in_sizes, int n_in,
                              void* d_out, int out_size)
{
    const float* pc = (const float*)d_in[0];
    const float* tw = (const float*)d_in[1];
    const float* tb = (const float*)d_in[2];
    const float* pw = (const float*)d_in[3];
    const float* pb = (const float*)d_in[4];
    const float* gw = (const float*)d_in[5];
    const float* gb = (const float*)d_in[6];
    const float* rw = (const float*)d_in[7];
    const float* rb = (const float*)d_in[8];
    float* out = (float*)d_out;

    cudaFuncSetAttribute(attn_y_kernel,
                         cudaFuncAttributeMaxDynamicSharedMemorySize, AT_SMEM);
    cudaFuncSetAttribute(refine_kernel,
                         cudaFuncAttributeMaxDynamicSharedMemorySize, RF_SMEM);

    proj_kernel   <<<dim3(16, 3, BATCH), 256>>>(pc, tw, tb, pw, pb, gw, gb);
    scores_kernel <<<dim3(16, 16, BATCH), 256, SC_SMEM>>>();
    scalegT_kernel<<<dim3(32, BATCH), 256>>>();
    attn_y_kernel <<<dim3(32, BATCH), 256, AT_SMEM>>>();
    refine_kernel <<<dim3(32, BATCH), 256, RF_SMEM>>>(rw, rb);
    scatter_kernel<<<2048, 256>>>(pc, out);
}

// round 16
// speedup vs baseline: 2.1931x; 1.0643x over previous
#include <cuda_runtime.h>
#include <cuda_bf16.h>

#define BATCH 8
#define CH    128
#define MIDC  64
#define OUTC  128
#define TN    2048

typedef unsigned long long u64;
typedef unsigned int u32;

// ---------------------------------------------------------------------------
// Scratch (device globals; allocation-free per harness rules)
// ---------------------------------------------------------------------------
__device__ __nv_bfloat16 g_thhi[BATCH * TN * MIDC];     // theta hi [b][q][m]
__device__ __nv_bfloat16 g_phhi[BATCH * TN * MIDC];     // phi hi [b][k][m]
__device__ __nv_bfloat16 g_phlo[BATCH * TN * MIDC];     // phi lo
__device__ float         g_g   [BATCH * TN * MIDC];     // g fp32 [b][k][m]
__device__ __nv_bfloat16 g_Ehi [(size_t)BATCH * TN * TN]; // exp(s) bf16 [b][q][k]
__device__ float g_Zp  [16 * BATCH * TN];
__device__ __nv_bfloat16 g_gsThi[BATCH * MIDC * TN];    // (g*invZ)^T bf16 [b][m][k]
__device__ __nv_bfloat16 g_yhi [BATCH * TN * MIDC];     // y hi bf16 [b][q][m]
__device__ __nv_bfloat16 g_ylo [BATCH * TN * MIDC];     // y lo bf16 [b][q][m]
__device__ float g_ref[BATCH * TN * OUTC];              // [b][q][o]

// ---------------------------------------------------------------------------
// PTX helpers (base ISA only)
// ---------------------------------------------------------------------------
__device__ __forceinline__ u32 smem_u32(const void* p) {
    u32 a; asm("{ .reg .u64 t; cvta.to.shared.u64 t, %1; cvt.u32.u64 %0, t; }"
               : "=r"(a) : "l"(p)); return a;
}
#define SWZ128(x) ((x) ^ (((x) >> 3) & 0x70))

__device__ __forceinline__ void ldsm4(u32* r, u32 addr) {
    asm volatile("ldmatrix.sync.aligned.m8n8.x4.shared.b16 {%0,%1,%2,%3}, [%4];"
        : "=r"(r[0]), "=r"(r[1]), "=r"(r[2]), "=r"(r[3]) : "r"(addr));
}
__device__ __forceinline__ void mma16816(float* d, const u32* a, u32 b0, u32 b1) {
    asm volatile("mma.sync.aligned.m16n8k16.row.col.f32.bf16.bf16.f32 "
        "{%0,%1,%2,%3}, {%4,%5,%6,%7}, {%8,%9}, {%0,%1,%2,%3};"
        : "+f"(d[0]), "+f"(d[1]), "+f"(d[2]), "+f"(d[3])
        : "r"(a[0]), "r"(a[1]), "r"(a[2]), "r"(a[3]), "r"(b0), "r"(b1));
}
#define CPA16(dst, src) \
    asm volatile("cp.async.cg.shared.global [%0], [%1], 16;" \
                 :: "r"(dst), "l"(src) : "memory")
#define CPA_COMMIT() asm volatile("cp.async.commit_group;" ::: "memory")

// fp32x2 + fast exp helpers
__device__ __forceinline__ u64 splat2(float x) {
    u64 r; asm("mov.b64 %0,{%1,%1};" : "=l"(r) : "f"(x)); return r;
}
__device__ __forceinline__ u64 fma2_(u64 a, u64 b, u64 c) {
    u64 d; asm("fma.rn.f32x2 %0,%1,%2,%3;" : "=l"(d) : "l"(a), "l"(b), "l"(c)); return d;
}
__device__ __forceinline__ void upk2(u64 p, float& a, float& b) {
    asm("mov.b64 {%0,%1},%2;" : "=f"(a), "=f"(b) : "l"(p));
}
__device__ __forceinline__ float fexp(float x) {
    const float L2E = 1.4426950408889634f;
    float z = fmaf(x, L2E, 12582912.0f);
    float n = z - 12582912.0f;
    float f = fmaf(x, L2E, -n);
    float p =          1.3333558146e-3f;
    p = fmaf(p, f,     9.6181291076e-3f);
    p = fmaf(p, f,     5.5504108665e-2f);
    p = fmaf(p, f,     2.4022650696e-1f);
    p = fmaf(p, f,     6.9314718056e-1f);
    p = fmaf(p, f,     1.0f);
    int ni = __float_as_int(z) - 0x4B400000;
    return p * __int_as_float((ni + 127) << 23);
}
__device__ __forceinline__ u32 pkbf(__nv_bfloat16 a, __nv_bfloat16 b) {
    return (u32)__bfloat16_as_ushort(a) | ((u32)__bfloat16_as_ushort(b) << 16);
}
__device__ __forceinline__ u32 pk_hi2(float x, float y) {
    return pkbf(__float2bfloat16(x), __float2bfloat16(y));
}
__device__ __forceinline__ u32 pk_lo2(float x, float y) {
    __nv_bfloat16 hx = __float2bfloat16(x), hy = __float2bfloat16(y);
    return pkbf(__float2bfloat16(x - __bfloat162float(hx)),
                __float2bfloat16(y - __bfloat162float(hy)));
}

// ---------------------------------------------------------------------------
// 1) Merged projections: one block computes theta/phi/g for its tn-tile,
//    reading pc ONCE.  tn-tile 64; grid (32, BATCH).
// ---------------------------------------------------------------------------
__global__ void __launch_bounds__(256)
proj_kernel(const float* __restrict__ pc,
            const float* __restrict__ tw, const float* __restrict__ tb,
            const float* __restrict__ pw, const float* __restrict__ pb,
            const float* __restrict__ gw, const float* __restrict__ gb)
{
    __shared__ __align__(16) float As3[3 * 32 * 64];   // W^T chunks [pj][cc][m]
    __shared__ __align__(16) float Bs[32 * 64];        // pc chunk  [cc][tn]
    const int b = blockIdx.y;
    const int n0 = blockIdx.x * 64;
    const float* Ws[3] = { tw, pw, gw };
    const float* pcb = pc + (size_t)b * CH * TN;
    const int tid = threadIdx.x;
    const int tx = tid & 7, ty = tid >> 3;   // tx: tn oct (8), ty: mid pair (32)

    u64 acc[3][2][4];
#pragma unroll
    for (int pj = 0; pj < 3; pj++)
#pragma unroll
        for (int i = 0; i < 2; i++)
#pragma unroll
            for (int j = 0; j < 4; j++) acc[pj][i][j] = 0ULL;

    for (int ct = 0; ct < 128; ct += 32) {
#pragma unroll
        for (int pj = 0; pj < 3; pj++)
#pragma unroll
            for (int t = 0; t < 2; t++) {
                int f4 = tid + t * 256;              // 0..511
                int m = f4 >> 3, c4 = (f4 & 7) << 2;
                float4 w4 = *(const float4*)&Ws[pj][m * 128 + ct + c4];
                As3[pj * 2048 + (c4 + 0) * 64 + m] = w4.x;
                As3[pj * 2048 + (c4 + 1) * 64 + m] = w4.y;
                As3[pj * 2048 + (c4 + 2) * 64 + m] = w4.z;
                As3[pj * 2048 + (c4 + 3) * 64 + m] = w4.w;
            }
#pragma unroll
        for (int t = 0; t < 2; t++) {
            int f4 = tid + t * 256;                  // 0..511
            int cc = f4 >> 4, c4 = (f4 & 15) << 2;
            *(float4*)&Bs[cc * 64 + c4] =
                *(const float4*)&pcb[(size_t)(ct + cc) * TN + n0 + c4];
        }
        __syncthreads();
#pragma unroll 4
        for (int cc = 0; cc < 32; cc++) {
            ulonglong2 b01 = *(ulonglong2*)&Bs[cc * 64 + tx * 8];
            ulonglong2 b23 = *(ulonglong2*)&Bs[cc * 64 + tx * 8 + 4];
            u64 bb[4] = { b01.x, b01.y, b23.x, b23.y };
#pragma unroll
            for (int pj = 0; pj < 3; pj++) {
                float2 a2 = *(float2*)&As3[pj * 2048 + cc * 64 + ty * 2];
                u64 a0 = splat2(a2.x), a1 = splat2(a2.y);
#pragma unroll
                for (int j = 0; j < 4; j++) {
                    acc[pj][0][j] = fma2_(a0, bb[j], acc[pj][0][j]);
                    acc[pj][1][j] = fma2_(a1, bb[j], acc[pj][1][j]);
                }
            }
        }
        __syncthreads();
    }

    // epilogues
#pragma unroll
    for (int pj = 0; pj < 3; pj++) {
        const float* bi = (pj == 0) ? tb : (pj == 1) ? pb : gb;
        float v[2][8];
#pragma unroll
        for (int i = 0; i < 2; i++) {
#pragma unroll
            for (int j2 = 0; j2 < 4; j2++)
                upk2(acc[pj][i][j2], v[i][2 * j2], v[i][2 * j2 + 1]);
            float bv = bi[ty * 2 + i];
#pragma unroll
            for (int j = 0; j < 8; j++) v[i][j] = fmaxf(v[i][j] + bv, 0.f);
        }
        if (pj == 0) {
#pragma unroll
            for (int j = 0; j < 8; j++) {
                size_t row = (size_t)(b * TN + n0 + tx * 8 + j) * MIDC + ty * 2;
                *(u32*)&g_thhi[row] = pk_hi2(v[0][j], v[1][j]);
            }
        } else if (pj == 1) {
#pragma unroll
            for (int j = 0; j < 8; j++) {
                size_t row = (size_t)(b * TN + n0 + tx * 8 + j) * MIDC + ty * 2;
                *(u32*)&g_phhi[row] = pk_hi2(v[0][j], v[1][j]);
                *(u32*)&g_phlo[row] = pk_lo2(v[0][j], v[1][j]);
            }
        } else {
#pragma unroll
            for (int j = 0; j < 8; j++) {
                size_t row = (size_t)(b * TN + n0 + tx * 8 + j) * MIDC + ty * 2;
                *(float2*)&g_g[row] = make_float2(v[0][j], v[1][j]);
            }
        }
    }
}

// ---------------------------------------------------------------------------
// 2) scores: warp-MMA bf16 2-pass (th_hi x ph_hi + th_hi x ph_lo), fused
//    exp + register colsum, E hi store. cp.async operand loads.
// ---------------------------------------------------------------------------
#define SC_SMEM 49152
#define EST 272                                   // staging row stride bytes

__global__ void __launch_bounds__(256)
scores_kernel()
{
    extern __shared__ char smem[];
    const u32 sb = smem_u32(smem);
    const int b = blockIdx.z, qt = blockIdx.y, kt = blockIdx.x;
    const int q0 = qt * 128, k0 = kt * 128;
    const int tid = threadIdx.x, wid = tid >> 5, lane = tid & 31;
    const int wq = wid >> 1, wk = wid & 1;

    // load 3 operand tiles (128 rows x 64 bf16) swizzled, via cp.async
    {
        const __nv_bfloat16* s0 = g_thhi + (size_t)(b * TN + q0) * MIDC;
        const __nv_bfloat16* s1 = g_phhi + (size_t)(b * TN + k0) * MIDC;
        const __nv_bfloat16* s2 = g_phlo + (size_t)(b * TN + k0) * MIDC;
        const __nv_bfloat16* srcs[3] = { s0, s1, s2 };
#pragma unroll
        for (int it = 0; it < 12; it++) {
            int idx = tid + it * 256;            // 0..3071 16B units
            int mat = idx >> 10, row = (idx >> 3) & 127, u = idx & 7;
            CPA16(sb + mat * 16384 + SWZ128(row * 128 + u * 16),
                  (const void*)(srcs[mat] + (size_t)row * MIDC + u * 8));
        }
        CPA_COMMIT();
        asm volatile("cp.async.wait_group 0;" ::: "memory");
    }
    __syncthreads();

    float acc[2][8][4];
#pragma unroll
    for (int i = 0; i < 2; i++)
#pragma unroll
        for (int j = 0; j < 8; j++)
#pragma unroll
            for (int r = 0; r < 4; r++) acc[i][j][r] = 0.f;

    const int arow = wq * 32 + (lane & 15);
    const int acolx = (lane >> 4) << 4;
    const int brow = wk * 64 + (lane & 7) + ((lane >> 4) << 3);
    const int bcolx = ((lane >> 3) & 1) << 4;

#pragma unroll
    for (int ks = 0; ks < 4; ks++) {
        int kb = ks * 32;
        u32 aH0[4], aH1[4];
        ldsm4(aH0, sb + SWZ128(arow * 128 + kb + acolx));
        ldsm4(aH1, sb + SWZ128((arow + 16) * 128 + kb + acolx));
#pragma unroll
        for (int jp = 0; jp < 4; jp++) {
            u32 bH[4], bL[4];
            ldsm4(bH, sb + 16384 + SWZ128((brow + jp * 16) * 128 + kb + bcolx));
            ldsm4(bL, sb + 32768 + SWZ128((brow + jp * 16) * 128 + kb + bcolx));
            // hi * hi
            mma16816(acc[0][2 * jp],     aH0, bH[0], bH[1]);
            mma16816(acc[0][2 * jp + 1], aH0, bH[2], bH[3]);
            mma16816(acc[1][2 * jp],     aH1, bH[0], bH[1]);
            mma16816(acc[1][2 * jp + 1], aH1, bH[2], bH[3]);
            // hi * lo
            mma16816(acc[0][2 * jp],     aH0, bL[0], bL[1]);
            mma16816(acc[0][2 * jp + 1], aH0, bL[2], bL[3]);
            mma16816(acc[1][2 * jp],     aH1, bL[0], bL[1]);
            mma16816(acc[1][2 * jp + 1], aH1, bL[2], bL[3]);
        }
    }
    __syncthreads();                             // operands dead

    // exp in registers (fp32), stage E hi, per-column fp32 partial sums
    float* red = (float*)(smem + 128 * EST);     // 34816: [4 wq][128 k]
#pragma unroll
    for (int i = 0; i < 2; i++)
#pragma unroll
        for (int j = 0; j < 8; j++)
#pragma unroll
            for (int r = 0; r < 4; r++) acc[i][j][r] = fexp(acc[i][j][r]);

#pragma unroll
    for (int i = 0; i < 2; i++) {
        int qr = wq * 32 + i * 16 + (lane >> 2);
#pragma unroll
        for (int j = 0; j < 8; j++) {
            int kc = wk * 64 + j * 8 + 2 * (lane & 3);
            *(u32*)(smem + qr * EST + kc * 2)       = pk_hi2(acc[i][j][0], acc[i][j][1]);
            *(u32*)(smem + (qr + 8) * EST + kc * 2) = pk_hi2(acc[i][j][2], acc[i][j][3]);
        }
    }
#pragma unroll
    for (int j = 0; j < 8; j++) {
        float c0 = (acc[0][j][0] + acc[0][j][2]) + (acc[1][j][0] + acc[1][j][2]);
        float c1 = (acc[0][j][1] + acc[0][j][3]) + (acc[1][j][1] + acc[1][j][3]);
#pragma unroll
        for (int off = 4; off < 32; off <<= 1) {
            c0 += __shfl_xor_sync(0xFFFFFFFFu, c0, off);
            c1 += __shfl_xor_sync(0xFFFFFFFFu, c1, off);
        }
        if (lane < 4) {
            int kc = wk * 64 + j * 8 + 2 * lane;
            red[wq * 128 + kc]     = c0;
            red[wq * 128 + kc + 1] = c1;
        }
    }
    __syncthreads();

    if (tid < 128) {
        float z = (red[tid] + red[128 + tid]) + (red[256 + tid] + red[384 + tid]);
        g_Zp[(qt * BATCH + b) * TN + k0 + tid] = z;
    }

    // coalesced copy-out of E hi: 2 rows per warp per pass, uint4 (16-aligned)
    for (int rp = wid * 2; rp < 128; rp += 16) {
        int row = rp + (lane >> 4);
        int u = lane & 15;
        uint4 v = *(const uint4*)(smem + row * EST + u * 16);
        *(uint4*)&g_Ehi[(size_t)(b * TN + q0 + row) * TN + k0 + u * 8] = v;
    }
}

// ---------------------------------------------------------------------------
// 3) scalegT (invZ fused): gsT [m][k] = bf16(g[k][m]/Z[k])
// ---------------------------------------------------------------------------
__global__ void __launch_bounds__(256)
scalegT_kernel()
{
    __shared__ float s[64][65];
    __shared__ float siz[64];
    const int k0 = blockIdx.x * 64, b = blockIdx.y;
    const int tid = threadIdx.x;
    if (tid < 64) {
        int idx = b * TN + k0 + tid;
        float z = 0.f;
#pragma unroll
        for (int t = 0; t < 16; t++) z += g_Zp[t * 16384 + idx];
        siz[tid] = 1.0f / z;
    }
    __syncthreads();
#pragma unroll
    for (int t = 0; t < 4; t++) {
        int f4 = tid + t * 256;
        int row = f4 >> 4, c4 = (f4 & 15) << 2;
        float iz = siz[row];
        float4 v = *(const float4*)&g_g[(size_t)(b * TN + k0 + row) * MIDC + c4];
        s[row][c4 + 0] = v.x * iz;  s[row][c4 + 1] = v.y * iz;
        s[row][c4 + 2] = v.z * iz;  s[row][c4 + 3] = v.w * iz;
    }
    __syncthreads();
    int m = tid >> 2, kk0 = (tid & 3) << 4;
    u32 hw[8];
#pragma unroll
    for (int j = 0; j < 8; j++)
        hw[j] = pk_hi2(s[kk0 + 2 * j][m], s[kk0 + 2 * j + 1][m]);
    size_t doff = (size_t)(b * MIDC + m) * TN + k0 + kk0;
    *(uint4*)&g_gsThi[doff]     = make_uint4(hw[0], hw[1], hw[2], hw[3]);
    *(uint4*)&g_gsThi[doff + 8] = make_uint4(hw[4], hw[5], hw[6], hw[7]);
}

// ---------------------------------------------------------------------------
// 4) attn_y: y[q][m] = sum_k Ehi[q][k] * gsT[k][m].
//    k-chunk 128, 3-stage cp.async pipeline (32KB/stage), 1 barrier/chunk.
//    Epilogue: pack fragments directly to y hi/lo bf16 [q][m] (no staging).
// ---------------------------------------------------------------------------
#define AT_SMEM 98304

__global__ void __launch_bounds__(256)
attn_y_kernel()
{
    extern __shared__ char smem[];
    const u32 sb = smem_u32(smem);
    const int qt = blockIdx.x, b = blockIdx.y;
    const int q0 = qt * 64;
    const int tid = threadIdx.x, wid = tid >> 5, lane = tid & 31;
    const int wq = wid >> 1, wm = wid & 1;

    float acc[4][4];
#pragma unroll
    for (int j = 0; j < 4; j++)
#pragma unroll
        for (int r = 0; r < 4; r++) acc[j][r] = 0.f;

    const int arow = wq * 16 + (lane & 15);
    const int acolx = (lane >> 4) << 4;
    const int brow = wm * 32 + (lane & 7) + ((lane >> 4) << 3);
    const int bcolx = ((lane >> 3) & 1) << 4;

    // stage layout (32KB): E0 @0, E1 @8192, gs0 @16384, gs1 @24576
    auto load_stage = [&](int stage, int kc) {
        u32 base = sb + stage * 32768;
#pragma unroll
        for (int it = 0; it < 4; it++) {         // E: 1024 16B units
            int idx = tid + it * 256;
            int half = idx >> 9, row = (idx >> 3) & 63, u = idx & 7;
            CPA16(base + half * 8192 + SWZ128(row * 128 + u * 16),
                  (const void*)&g_Ehi[(size_t)(b * TN + q0 + row) * TN
                                      + kc + half * 64 + u * 8]);
        }
#pragma unroll
        for (int it = 0; it < 4; it++) {         // gs: 1024 16B units
            int idx = tid + it * 256;
            int half = idx >> 9, row = (idx >> 3) & 63, u = idx & 7;
            CPA16(base + 16384 + half * 8192 + SWZ128(row * 128 + u * 16),
                  (const void*)&g_gsThi[(size_t)(b * MIDC + row) * TN
                                        + kc + half * 64 + u * 8]);
        }
        CPA_COMMIT();
    };

    load_stage(0, 0);
    load_stage(1, 128);
    for (int ch = 0; ch < 16; ch++) {
        if (ch == 15) asm volatile("cp.async.wait_group 0;" ::: "memory");
        else          asm volatile("cp.async.wait_group 1;" ::: "memory");
        __syncthreads();                         // buffer ch visible; MMA(ch-1) done
        if (ch + 2 < 16) load_stage((ch + 2) % 3, (ch + 2) * 128);
        u32 base = sb + (ch % 3) * 32768;
#pragma unroll
        for (int half = 0; half < 2; half++) {
            u32 bA = base + half * 8192;
            u32 bB = base + 16384 + half * 8192;
#pragma unroll
            for (int ks = 0; ks < 4; ks++) {
                int kb = ks * 32;
                u32 a0[4];
                ldsm4(a0, bA + SWZ128(arow * 128 + kb + acolx));
#pragma unroll
                for (int jp = 0; jp < 2; jp++) {
                    u32 bb[4];
                    ldsm4(bb, bB + SWZ128((brow + jp * 16) * 128 + kb + bcolx));
                    mma16816(acc[2 * jp],     a0, bb[0], bb[1]);
                    mma16816(acc[2 * jp + 1], a0, bb[2], bb[3]);
                }
            }
        }
    }

    // epilogue: pack fragments to y hi/lo bf16 [b][q][m] (register-only)
    {
        int qr = wq * 16 + (lane >> 2);
#pragma unroll
        for (int j = 0; j < 4; j++) {
            int mc = wm * 32 + j * 8 + 2 * (lane & 3);
            size_t r0 = (size_t)(b * TN + q0 + qr) * MIDC + mc;
            size_t r1 = (size_t)(b * TN + q0 + qr + 8) * MIDC + mc;
            *(u32*)&g_yhi[r0] = pk_hi2(acc[j][0], acc[j][1]);
            *(u32*)&g_ylo[r0] = pk_lo2(acc[j][0], acc[j][1]);
            *(u32*)&g_yhi[r1] = pk_hi2(acc[j][2], acc[j][3]);
            *(u32*)&g_ylo[r1] = pk_lo2(acc[j][2], acc[j][3]);
        }
    }
}

// ---------------------------------------------------------------------------
// 5) refine: 3-pass bf16 HMMA. refined[q][o] = relu(y[q][m]*rw[o][m] + rb[o])
// ---------------------------------------------------------------------------
#define RF_SMEM 49664

__global__ void __launch_bounds__(256)
refine_kernel(const float* __restrict__ RW, const float* __restrict__ RB)
{
    extern __shared__ char smem[];
    const u32 sb = smem_u32(smem);
    const int b = blockIdx.y;
    const int q0 = blockIdx.x * 64;
    const int tid = threadIdx.x, wid = tid >> 5, lane = tid & 31;
    const int wq = wid >> 2, wo = wid & 3;
    float* bias = (float*)(smem + 49152);

    {
        const __nv_bfloat16* s0 = g_yhi + (size_t)(b * TN + q0) * MIDC;
        const __nv_bfloat16* s1 = g_ylo + (size_t)(b * TN + q0) * MIDC;
#pragma unroll
        for (int it = 0; it < 4; it++) {
            int idx = tid + it * 256;            // 0..1023
            int mat = idx >> 9, row = (idx >> 3) & 63, u = idx & 7;
            CPA16(sb + mat * 8192 + SWZ128(row * 128 + u * 16),
                  (const void*)((mat ? s1 : s0) + (size_t)row * MIDC + u * 8));
        }
        CPA_COMMIT();
    }
#pragma unroll
    for (int t = 0; t < 8; t++) {
        int f4 = tid + t * 256;                  // 0..2047
        int o = f4 >> 4, m4 = (f4 & 15) << 2;
        float4 w = *(const float4*)&RW[o * MIDC + m4];
        u32 off = SWZ128(o * 128 + m4 * 2);
        *(u64*)(smem + 16384 + off) =
            ((u64)pk_hi2(w.z, w.w) << 32) | pk_hi2(w.x, w.y);
        *(u64*)(smem + 32768 + off) =
            ((u64)pk_lo2(w.z, w.w) << 32) | pk_lo2(w.x, w.y);
    }
    if (tid < 128) bias[tid] = RB[tid];
    asm volatile("cp.async.wait_group 0;" ::: "memory");
    __syncthreads();

    float acc[2][4][4];
#pragma unroll
    for (int i = 0; i < 2; i++)
#pragma unroll
        for (int j = 0; j < 4; j++)
#pragma unroll
            for (int r = 0; r < 4; r++) acc[i][j][r] = 0.f;

    const int arow = wq * 32 + (lane & 15);
    const int acolx = (lane >> 4) << 4;
    const int brow = wo * 32 + (lane & 7) + ((lane >> 4) << 3);
    const int bcolx = ((lane >> 3) & 1) << 4;

#pragma unroll
    for (int ks = 0; ks < 4; ks++) {
        int kb = ks * 32;
        u32 aH0[4], aH1[4], aL0[4], aL1[4];
        ldsm4(aH0, sb        + SWZ128(arow * 128 + kb + acolx));
        ldsm4(aH1, sb        + SWZ128((arow + 16) * 128 + kb + acolx));
        ldsm4(aL0, sb + 8192 + SWZ128(arow * 128 + kb + acolx));
        ldsm4(aL1, sb + 8192 + SWZ128((arow + 16) * 128 + kb + acolx));
#pragma unroll
        for (int jp = 0; jp < 2; jp++) {
            u32 bH[4], bL[4];
            ldsm4(bH, sb + 16384 + SWZ128((brow + jp * 16) * 128 + kb + bcolx));
            ldsm4(bL, sb + 32768 + SWZ128((brow + jp * 16) * 128 + kb + bcolx));
            mma16816(acc[0][2 * jp],     aH0, bH[0], bH[1]);
            mma16816(acc[0][2 * jp + 1], aH0, bH[2], bH[3]);
            mma16816(acc[1][2 * jp],     aH1, bH[0], bH[1]);
            mma16816(acc[1][2 * jp + 1], aH1, bH[2], bH[3]);
            mma16816(acc[0][2 * jp],     aH0, bL[0], bL[1]);
            mma16816(acc[0][2 * jp + 1], aH0, bL[2], bL[3]);
            mma16816(acc[1][2 * jp],     aH1, bL[0], bL[1]);
            mma16816(acc[1][2 * jp + 1], aH1, bL[2], bL[3]);
            mma16816(acc[0][2 * jp],     aL0, bH[0], bH[1]);
            mma16816(acc[0][2 * jp + 1], aL0, bH[2], bH[3]);
            mma16816(acc[1][2 * jp],     aL1, bH[0], bH[1]);
            mma16816(acc[1][2 * jp + 1], aL1, bH[2], bH[3]);
        }
    }

    float* Rb = g_ref + (size_t)b * TN * OUTC;
#pragma unroll
    for (int i = 0; i < 2; i++) {
        int qr = q0 + wq * 32 + i * 16 + (lane >> 2);
#pragma unroll
        for (int j = 0; j < 4; j++) {
            int oc = wo * 32 + j * 8 + 2 * (lane & 3);
            float b0 = bias[oc], b1 = bias[oc + 1];
            float2 v0 = make_float2(fmaxf(acc[i][j][0] + b0, 0.f),
                                    fmaxf(acc[i][j][1] + b1, 0.f));
            float2 v1 = make_float2(fmaxf(acc[i][j][2] + b0, 0.f),
                                    fmaxf(acc[i][j][3] + b1, 0.f));
            *(float2*)&Rb[(size_t)qr * OUTC + oc]       = v0;
            *(float2*)&Rb[(size_t)(qr + 8) * OUTC + oc] = v1;
        }
    }
}

// ---------------------------------------------------------------------------
// 6) scatter via smem transpose: fully coalesced global traffic.
//    Block = (4-channel tile, b).  q=(n&15)*128+c, o=t*32+(n>>4).
//    smem rows: row = nlow*4 + cloc  holds  g_ref[b][nlow*128 + c0+cloc][:].
// ---------------------------------------------------------------------------
__global__ void __launch_bounds__(256)
scatter_kernel(const float* __restrict__ pc, float* __restrict__ out)
{
    __shared__ float sm[64 * 133];
    const int c0 = blockIdx.x * 4, b = blockIdx.y;
    const int tid = threadIdx.x;
    const float* Rb = g_ref + ((size_t)b << 18);

    // load 64 needed rows x 128 o, coalesced
#pragma unroll
    for (int t = 0; t < 8; t++) {
        int f4 = tid + t * 256;                  // 0..2047
        int row = f4 >> 5, o4 = (f4 & 31) << 2;
        int nlow = row >> 2, cloc = row & 3;
        float4 v = *(const float4*)&Rb[(size_t)((nlow << 7) + c0 + cloc) * OUTC + o4];
        sm[row * 133 + o4 + 0] = v.x;
        sm[row * 133 + o4 + 1] = v.y;
        sm[row * 133 + o4 + 2] = v.z;
        sm[row * 133 + o4 + 3] = v.w;
    }
    __syncthreads();

    // write out[b][c0..c0+4][t][n] coalesced; read pc coalesced
    size_t obase = ((size_t)b << 18) + (size_t)c0 * 2048;
#pragma unroll
    for (int t8 = 0; t8 < 8; t8++) {
        int f4 = tid + t8 * 256;                 // 0..2047
        int cloc = f4 >> 9;
        int rem = f4 & 511;                      // t*128 + n4g
        int n4g = rem & 127;
        int o = ((rem >> 7) << 5) + (n4g >> 2);
        int rbase = ((n4g & 3) << 4) + cloc;     // row for i=0; rows step by 4
        size_t oidx = obase + ((size_t)cloc << 11) + (size_t)(rem << 2);
        float4 p = *(const float4*)&pc[oidx];
        float4 v;
        v.x = sm[(rbase +  0) * 133 + o] + p.x;
        v.y = sm[(rbase +  4) * 133 + o] + p.y;
        v.z = sm[(rbase +  8) * 133 + o] + p.z;
        v.w = sm[(rbase + 12) * 133 + o] + p.w;
        *(float4*)&out[oidx] = v;
    }
}

// ---------------------------------------------------------------------------
// Host launcher
// ---------------------------------------------------------------------------
extern "C" void kernel_launch(void* const* d_in, const int* in_sizes, int n_in,
                              void* d_out, int out_size)
{
    const float* pc = (const float*)d_in[0];
    const float* tw = (const float*)d_in[1];
    const float* tb = (const float*)d_in[2];
    const float* pw = (const float*)d_in[3];
    const float* pb = (const float*)d_in[4];
    const float* gw = (const float*)d_in[5];
    const float* gb = (const float*)d_in[6];
    const float* rw = (const float*)d_in[7];
    const float* rb = (const float*)d_in[8];
    float* out = (float*)d_out;

    cudaFuncSetAttribute(attn_y_kernel,
                         cudaFuncAttributeMaxDynamicSharedMemorySize, AT_SMEM);
    cudaFuncSetAttribute(refine_kernel,
                         cudaFuncAttributeMaxDynamicSharedMemorySize, RF_SMEM);

    proj_kernel   <<<dim3(32, BATCH), 256>>>(pc, tw, tb, pw, pb, gw, gb);
    scores_kernel <<<dim3(16, 16, BATCH), 256, SC_SMEM>>>();
    scalegT_kernel<<<dim3(32, BATCH), 256>>>();
    attn_y_kernel <<<dim3(32, BATCH), 256, AT_SMEM>>>();
    refine_kernel <<<dim3(32, BATCH), 256, RF_SMEM>>>(rw, rb);
    scatter_kernel<<<dim3(32, BATCH), 256>>>(pc, out);
}